// round 13
// baseline (speedup 1.0000x reference)
#include <cuda_runtime.h>
#include <cuda_bf16.h>
#include <cstdint>

// ---------------- constants ----------------
#define Bb 256
#define Nn 128
#define Ww 16
#define Dd 64
#define TOPK 30
#define NW 2048               // N*W
#define BN_NODES 32768        // B*N
#define EPS 1e-5f

// hi/lo dedup layout: each bf16 buffer is [rows x 4096]: cols 0-2047 = hi, 2048-4095 = lo.
// Logical K = 6144 with region mapping: (A hi, W hi), (A lo, W hi), (A hi, W lo).

// ---------------- scratch ----------------
__device__ float d_lin[Bb * NW];
__device__ __align__(16) unsigned short d_abuf[Bb * 4096];
__device__ __align__(16) unsigned short d_wbuf4[4][NW * 4096];   // 64 MB: one per layer
__device__ float d_bnp[2 * 4 * NW];         // per-m-block BN partials: sums[4][NW], sqs[4][NW]
__device__ float d_cspart[16 * NW];
__device__ float d_embeds[Nn * Dd];
__device__ float d_ei[Nn];
__device__ float d_ej[Nn];
__device__ int   d_topkbuf[Nn * TOPK];
__device__ float d_xlin[BN_NODES * Dd];
__device__ float d_si[BN_NODES];
__device__ float d_sj[BN_NODES];
__device__ float d_agg[BN_NODES * Dd];
__device__ float d_tb[BN_NODES * Dd];
__device__ float d_part[128 * 128];
__device__ float d_stats1[128];
__device__ float d_stats2[128];

__device__ __forceinline__ uint32_t smem_u32(const void* p) {
    uint32_t a;
    asm("{ .reg .u64 t; cvta.to.shared.u64 t, %1; cvt.u32.u64 %0, t; }" : "=r"(a) : "l"(p));
    return a;
}
__device__ __forceinline__ void ldsm_x4(uint32_t& r0, uint32_t& r1, uint32_t& r2, uint32_t& r3,
                                        uint32_t addr) {
    asm volatile("ldmatrix.sync.aligned.m8n8.x4.shared.b16 {%0,%1,%2,%3}, [%4];"
                 : "=r"(r0), "=r"(r1), "=r"(r2), "=r"(r3) : "r"(addr));
}

// ---------------- hi/lo helpers ----------------
__device__ __forceinline__ void f4_to_hilo(float4 x, uint2& hv, uint2& lv) {
    __nv_bfloat16 h0 = __float2bfloat16_rn(x.x), h1 = __float2bfloat16_rn(x.y);
    __nv_bfloat16 h2 = __float2bfloat16_rn(x.z), h3 = __float2bfloat16_rn(x.w);
    __nv_bfloat16 l0 = __float2bfloat16_rn(x.x - __bfloat162float(h0));
    __nv_bfloat16 l1 = __float2bfloat16_rn(x.y - __bfloat162float(h1));
    __nv_bfloat16 l2 = __float2bfloat16_rn(x.z - __bfloat162float(h2));
    __nv_bfloat16 l3 = __float2bfloat16_rn(x.w - __bfloat162float(h3));
    __nv_bfloat162 hA = __nv_bfloat162(h0, h1), hB = __nv_bfloat162(h2, h3);
    __nv_bfloat162 lA = __nv_bfloat162(l0, l1), lB = __nv_bfloat162(l2, l3);
    hv.x = *(uint32_t*)&hA; hv.y = *(uint32_t*)&hB;
    lv.x = *(uint32_t*)&lA; lv.y = *(uint32_t*)&lB;
}

// ---------------- convert: X fp32 [rows x 2048] -> Y bf16 [rows x 4096] = [hi|lo] ----------------
__global__ void conv_hilo_kernel(const float* __restrict__ X, unsigned short* __restrict__ Y) {
    int idx = blockIdx.x * 256 + threadIdx.x;
    int m = idx >> 9, k4 = (idx & 511) << 2;
    float4 x = *(const float4*)(X + (size_t)m * NW + k4);
    uint2 hv, lv;
    f4_to_hilo(x, hv, lv);
    unsigned short* yr = Y + (size_t)m * 4096 + k4;
    *(uint2*)yr = hv;
    *(uint2*)(yr + 2048) = lv;
}

// ---------------- HMMA GEMM + fused BN column partials ----------------
// CTA tile 64x64, 512 threads (16 warps as 4m x 4n, warp tile 16x16),
// k-step 128, 3-stage dynamic smem pipeline.
#define SMST 136
#define STAGE_SH (64 * SMST)
__global__ void __launch_bounds__(512, 1)
gemm_mma_kernel(const unsigned short* __restrict__ Ag, const unsigned short* __restrict__ Wg,
                const float* __restrict__ bias, float* __restrict__ C, float* __restrict__ bnp) {
    extern __shared__ unsigned short sh[];
    __shared__ float s_sum[4][64], s_sq[4][64];
    int tid = threadIdx.x, wid = tid >> 5, lane = tid & 31;
    int wm = wid >> 2, wn = wid & 3;        // 4 m-warps x 4 n-warps
    int m0 = blockIdx.y * 64, n0 = blockIdx.x * 64;
    int g = lane >> 2, t = lane & 3;

    float acc[2][4];
#pragma unroll
    for (int ni = 0; ni < 2; ni++)
#pragma unroll
        for (int q = 0; q < 4; q++) acc[ni][q] = 0.f;

    // loader: per stage per matrix: 64 rows x 16 chunks(16B) = 1024 chunks; 512 thr x 2 iters each
    auto load_stage = [&](int st, int s) {
        int kb = s * 128;
        int r = kb >> 11, koff = kb & 2047;
        int aoff = (r == 1) ? 2048 : 0;
        int woff = (r == 2) ? 2048 : 0;
        unsigned short* as = sh + st * 2 * STAGE_SH;
        unsigned short* bs = as + STAGE_SH;
#pragma unroll
        for (int i = 0; i < 2; i++) {
            int id = i * 512 + tid;
            int row = id >> 4, c16 = (id & 15) * 8;
            uint32_t dA = smem_u32(as + row * SMST + c16);
            const void* sA = Ag + (size_t)(m0 + row) * 4096 + aoff + koff + c16;
            asm volatile("cp.async.cg.shared.global [%0], [%1], 16;" :: "r"(dA), "l"(sA));
            uint32_t dB = smem_u32(bs + row * SMST + c16);
            const void* sB = Wg + (size_t)(n0 + row) * 4096 + woff + koff + c16;
            asm volatile("cp.async.cg.shared.global [%0], [%1], 16;" :: "r"(dB), "l"(sB));
        }
        asm volatile("cp.async.commit_group;" ::: "memory");
    };

    load_stage(0, 0);
    load_stage(1, 1);

    const int NS = 48;
    int arow = wm * 16 + (lane & 15);
    int acol8 = (lane >> 4) << 3;
    int bnrow = wn * 16 + ((lane >> 4) << 3) + (lane & 7);
    int bcol8 = ((lane >> 3) & 1) << 3;
    for (int s = 0; s < NS; s++) {
        if (s < NS - 1) asm volatile("cp.async.wait_group 1;" ::: "memory");
        else            asm volatile("cp.async.wait_group 0;" ::: "memory");
        __syncthreads();
        if (s + 2 < NS) load_stage((s + 2) % 3, s + 2);

        const unsigned short* as = sh + (s % 3) * 2 * STAGE_SH;
        const unsigned short* bs = as + STAGE_SH;
#pragma unroll
        for (int ks = 0; ks < 8; ks++) {
            int kc = ks * 16;
            uint32_t a0, a1, a2, a3;
            ldsm_x4(a0, a1, a2, a3, smem_u32(as + arow * SMST + kc + acol8));
            uint32_t b0, b1, b2, b3;
            ldsm_x4(b0, b1, b2, b3, smem_u32(bs + bnrow * SMST + kc + bcol8));
#define MMA(ACC, B0, B1) \
            asm volatile("mma.sync.aligned.m16n8k16.row.col.f32.bf16.bf16.f32 " \
                         "{%0,%1,%2,%3}, {%4,%5,%6,%7}, {%8,%9}, {%0,%1,%2,%3};" \
                         : "+f"(ACC[0]), "+f"(ACC[1]), "+f"(ACC[2]), "+f"(ACC[3]) \
                         : "r"(a0), "r"(a1), "r"(a2), "r"(a3), "r"(B0), "r"(B1))
            MMA(acc[0], b0, b1);
            MMA(acc[1], b2, b3);
#undef MMA
        }
    }
    __syncthreads();

    // ---- epilogue: bias add, C store, per-column BN partials ----
    int row = m0 + wm * 16 + g;
    float csum[4], csq[4];
#pragma unroll
    for (int ni = 0; ni < 2; ni++) {
        int col = n0 + wn * 16 + ni * 8 + 2 * t;
        float2 bi = *(const float2*)(bias + col);
        float* c = acc[ni];
        float v0 = c[0] + bi.x, v1 = c[1] + bi.y;
        float v2 = c[2] + bi.x, v3 = c[3] + bi.y;
        float2 o0; o0.x = v0; o0.y = v1;
        float2 o1; o1.x = v2; o1.y = v3;
        *(float2*)(C + (size_t)row * NW + col) = o0;
        *(float2*)(C + (size_t)(row + 8) * NW + col) = o1;
        csum[ni * 2]     = v0 + v2;
        csum[ni * 2 + 1] = v1 + v3;
        csq[ni * 2]      = v0 * v0 + v2 * v2;
        csq[ni * 2 + 1]  = v1 * v1 + v3 * v3;
    }
#pragma unroll
    for (int o = 4; o <= 16; o <<= 1) {
#pragma unroll
        for (int q = 0; q < 4; q++) {
            csum[q] += __shfl_xor_sync(0xFFFFFFFFu, csum[q], o);
            csq[q]  += __shfl_xor_sync(0xFFFFFFFFu, csq[q],  o);
        }
    }
    if (g == 0) {
#pragma unroll
        for (int ni = 0; ni < 2; ni++) {
            int cl = wn * 16 + ni * 8 + 2 * t;
            s_sum[wm][cl]     = csum[ni * 2];
            s_sum[wm][cl + 1] = csum[ni * 2 + 1];
            s_sq[wm][cl]      = csq[ni * 2];
            s_sq[wm][cl + 1]  = csq[ni * 2 + 1];
        }
    }
    __syncthreads();
    if (tid < 64) {
        float s = s_sum[0][tid] + s_sum[1][tid] + s_sum[2][tid] + s_sum[3][tid];
        float q = s_sq[0][tid] + s_sq[1][tid] + s_sq[2][tid] + s_sq[3][tid];
        bnp[blockIdx.y * NW + n0 + tid]          = s;
        bnp[4 * NW + blockIdx.y * NW + n0 + tid] = q;
    }
}

// ---------------- BN apply + sigmoid with inline stats finalize; optional bf16 emit ----------
template <int EMIT>
__global__ void bn_apply_sig_kernel(const float* __restrict__ X, const float* __restrict__ bnp,
                                    const float* __restrict__ g, const float* __restrict__ b,
                                    float* __restrict__ Y, unsigned short* __restrict__ Ab) {
    int idx4 = blockIdx.x * blockDim.x + threadIdx.x;
    int m = idx4 >> 9, c4 = (idx4 & 511) << 2;
    float4 x  = *(const float4*)(X + (size_t)idx4 * 4);
    float4 gg = *(const float4*)(g + c4);
    float4 bb = *(const float4*)(b + c4);
    float4 mm, rs;
    {
        float4 s0 = *(const float4*)(bnp + c4);
        float4 s1 = *(const float4*)(bnp + NW + c4);
        float4 s2 = *(const float4*)(bnp + 2 * NW + c4);
        float4 s3 = *(const float4*)(bnp + 3 * NW + c4);
        float4 q0 = *(const float4*)(bnp + 4 * NW + c4);
        float4 q1 = *(const float4*)(bnp + 5 * NW + c4);
        float4 q2 = *(const float4*)(bnp + 6 * NW + c4);
        float4 q3 = *(const float4*)(bnp + 7 * NW + c4);
        mm.x = (s0.x + s1.x + s2.x + s3.x) * (1.f / 256.f);
        mm.y = (s0.y + s1.y + s2.y + s3.y) * (1.f / 256.f);
        mm.z = (s0.z + s1.z + s2.z + s3.z) * (1.f / 256.f);
        mm.w = (s0.w + s1.w + s2.w + s3.w) * (1.f / 256.f);
        rs.x = rsqrtf((q0.x + q1.x + q2.x + q3.x) * (1.f / 256.f) - mm.x * mm.x + EPS);
        rs.y = rsqrtf((q0.y + q1.y + q2.y + q3.y) * (1.f / 256.f) - mm.y * mm.y + EPS);
        rs.z = rsqrtf((q0.z + q1.z + q2.z + q3.z) * (1.f / 256.f) - mm.z * mm.z + EPS);
        rs.w = rsqrtf((q0.w + q1.w + q2.w + q3.w) * (1.f / 256.f) - mm.w * mm.w + EPS);
    }
    float4 o;
    o.x = 1.f / (1.f + expf(-((x.x - mm.x) * rs.x * gg.x + bb.x)));
    o.y = 1.f / (1.f + expf(-((x.y - mm.y) * rs.y * gg.y + bb.y)));
    o.z = 1.f / (1.f + expf(-((x.z - mm.z) * rs.z * gg.z + bb.z)));
    o.w = 1.f / (1.f + expf(-((x.w - mm.w) * rs.w * gg.w + bb.w)));
    *(float4*)(Y + (size_t)idx4 * 4) = o;
    if (EMIT) {
        uint2 hv, lv;
        f4_to_hilo(o, hv, lv);
        unsigned short* yr = Ab + (size_t)m * 4096 + c4;
        *(uint2*)yr = hv;
        *(uint2*)(yr + 2048) = lv;
    }
}

// ---------------- rho_hat = column sums of z ----------------
__global__ void colsum_part_kernel(const float* __restrict__ X, float* __restrict__ part) {
    int c = blockIdx.x * 256 + threadIdx.x;
    int r0 = blockIdx.y * 16;
    float s = 0.f;
#pragma unroll
    for (int r = 0; r < 16; r++) s += X[(size_t)(r0 + r) * NW + c];
    part[blockIdx.y * NW + c] = s;
}
__global__ void colsum_fin_kernel(const float* __restrict__ part, float* __restrict__ out) {
    int c = blockIdx.x * 256 + threadIdx.x;
    float s = 0.f;
#pragma unroll
    for (int i = 0; i < 16; i++) s += part[i * NW + c];
    out[c] = s;
}

// ---------------- misc: all_emb + y_process + rhos ----------------
__device__ __forceinline__ uint32_t rotl32(uint32_t x, uint32_t r) { return (x << r) | (x >> (32 - r)); }
__device__ __forceinline__ float tf_uniform(uint32_t bits) {
    uint32_t ub = (bits >> 9) | 0x3F800000u;
    float u = __uint_as_float(ub) - 1.0f;
    float v = u * (0.01f - 1e-5f) + 1e-5f;
    return fmaxf(1e-5f, v);
}
__global__ void misc_kernel(const float* __restrict__ embeds, float* __restrict__ allemb,
                            float* __restrict__ yp, float* __restrict__ rhos) {
    int idx = blockIdx.x * 256 + threadIdx.x;
    allemb[idx] = embeds[idx & 8191];
    if (idx < BN_NODES) yp[idx] = (float)(idx >> 13);
    if (idx < 2048) {
        const uint32_t k0 = 0u, k1 = 42u;
        uint32_t ks[3] = {k0, k1, k0 ^ k1 ^ 0x1BD11BDAu};
        uint32_t x0 = 0u + ks[0];
        uint32_t x1 = (uint32_t)idx + ks[1];
        const uint32_t rot[2][4] = {{13u, 15u, 26u, 6u}, {17u, 29u, 16u, 24u}};
#pragma unroll
        for (int r = 0; r < 5; r++) {
#pragma unroll
            for (int j = 0; j < 4; j++) {
                x0 += x1;
                x1 = rotl32(x1, rot[r & 1][j]);
                x1 ^= x0;
            }
            x0 += ks[(r + 1) % 3];
            x1 += ks[(r + 2) % 3] + (uint32_t)(r + 1);
        }
        rhos[idx] = tf_uniform(x0 ^ x1);
    }
}

// ---------------- GRU embeddings ----------------
__global__ void gru_kernel(const float* __restrict__ emb, const float* __restrict__ Wih,
                           const float* __restrict__ bih, const float* __restrict__ bhh,
                           const float* __restrict__ att_em_i, const float* __restrict__ att_em_j,
                           float* __restrict__ embeds, float* __restrict__ ei, float* __restrict__ ej) {
    int node = blockIdx.x;
    int proc = node >> 5;
    int t = threadIdx.x;
    int dir = t / 96, g = t % 96;
    __shared__ float x[64], gi[2][96], xn[64];
    if (t < 64) x[t] = emb[(size_t)node * 64 + t];
    __syncthreads();
    for (int l = 0; l < 3; l++) {
        {
            size_t base = (((size_t)proc * 3 + l) * 2 + dir) * 96 + g;
            const float* Wr = Wih + base * 64;
            float s = bih[base];
#pragma unroll
            for (int k = 0; k < 64; k++) s += Wr[k] * x[k];
            gi[dir][g] = s;
        }
        __syncthreads();
        if (g < 32) {
            int j = g;
            size_t bb = (((size_t)proc * 3 + l) * 2 + dir) * 96;
            float rh = bhh[bb + j], zh = bhh[bb + 32 + j], nh = bhh[bb + 64 + j];
            float r  = 1.f / (1.f + expf(-(gi[dir][j] + rh)));
            float zz = 1.f / (1.f + expf(-(gi[dir][32 + j] + zh)));
            float n  = tanhf(gi[dir][64 + j] + r * nh);
            xn[dir * 32 + j] = (1.f - zz) * n;
        }
        __syncthreads();
        if (t < 64) x[t] = xn[t];
        __syncthreads();
    }
    if (t < 64) embeds[(size_t)node * 64 + t] = x[t];
    if (t == 0) {
        float si = 0.f, sj = 0.f;
        for (int d = 0; d < 64; d++) { si += x[d] * att_em_i[d]; sj += x[d] * att_em_j[d]; }
        ei[node] = si; ej[node] = sj;
    }
}

// ---------------- cosine-sim top-k ----------------
__global__ void topk_kernel(const float* __restrict__ embeds, int* __restrict__ topk) {
    __shared__ float en[128][65];
    int t = threadIdx.x;
    float row[64]; float s = 0.f;
    for (int d = 0; d < 64; d++) { float v = embeds[t * 64 + d]; row[d] = v; s += v * v; }
    float nrm = sqrtf(s);
    for (int d = 0; d < 64; d++) en[t][d] = row[d] / nrm;
    __syncthreads();
    float sim[128];
    for (int j = 0; j < 128; j++) {
        float acc = 0.f;
        for (int d = 0; d < 64; d++) acc += en[t][d] * en[j][d];
        sim[j] = acc;
    }
    for (int k = 0; k < TOPK; k++) {
        float best = -1e38f; int bi = 0;
        for (int j = 0; j < 128; j++) if (sim[j] > best) { best = sim[j]; bi = j; }
        topk[t * TOPK + k] = bi;
        sim[bi] = -1e38f;
    }
}

// ---------------- x_lin + per-node attention scores ----------------
__global__ void xlin_score_kernel(const float* __restrict__ z, const float* __restrict__ W,
                                  const float* __restrict__ att_i, const float* __restrict__ att_j,
                                  const float* __restrict__ ei, const float* __restrict__ ej,
                                  float* __restrict__ xlin, float* __restrict__ si, float* __restrict__ sj) {
    __shared__ float Ws[64][17];
    __shared__ float ai[64], aj[64];
    int t = threadIdx.x;
    if (t < 64) { ai[t] = att_i[t]; aj[t] = att_j[t]; }
    for (int idx = t; idx < 1024; idx += 256) Ws[idx >> 4][idx & 15] = W[idx];
    __syncthreads();
    int warp = t >> 5, lane = t & 31;
    int v = blockIdx.x * 8 + warp;
    float zr[16];
#pragma unroll
    for (int k = 0; k < 16; k++) zr[k] = z[(size_t)v * 16 + k];
    int d0 = lane, d1 = lane + 32;
    float x0 = 0.f, x1 = 0.f;
#pragma unroll
    for (int k = 0; k < 16; k++) { x0 += zr[k] * Ws[d0][k]; x1 += zr[k] * Ws[d1][k]; }
    xlin[(size_t)v * 64 + d0] = x0;
    xlin[(size_t)v * 64 + d1] = x1;
    float pi = x0 * ai[d0] + x1 * ai[d1];
    float pj = x0 * aj[d0] + x1 * aj[d1];
#pragma unroll
    for (int o = 16; o > 0; o >>= 1) {
        pi += __shfl_xor_sync(0xFFFFFFFFu, pi, o);
        pj += __shfl_xor_sync(0xFFFFFFFFu, pj, o);
    }
    if (lane == 0) {
        int i = v & 127;
        si[v] = pi + ei[i];
        sj[v] = pj + ej[i];
    }
}

// ---------------- GAT attention aggregation ----------------
__global__ void attn_kernel(const float* __restrict__ xlin, const float* __restrict__ si,
                            const float* __restrict__ sj, const int* __restrict__ topk,
                            const float* __restrict__ bias, float* __restrict__ agg) {
    int nl = threadIdx.x >> 6;
    int t  = threadIdx.x & 63;
    int v = blockIdx.x * 4 + nl;
    int i = v & 127, b = v >> 7;
    __shared__ float w[4][32];
    __shared__ int   srcv[4][31];
    __shared__ float invden[4];
    if (t < 32) {
        float a = -3e38f;
        if (t < 31) {
            int s, valid;
            if (t < 30) { s = topk[i * TOPK + t]; valid = (s != i); }
            else        { s = i; valid = 1; }
            int sv = (b << 7) + s;
            srcv[nl][t] = sv;
            float raw = si[v] + sj[sv];
            raw = raw > 0.f ? raw : 0.2f * raw;
            a = valid ? raw : -1e30f;
        }
        float mx = a;
#pragma unroll
        for (int o = 16; o > 0; o >>= 1) mx = fmaxf(mx, __shfl_xor_sync(0xFFFFFFFFu, mx, o));
        float ee = (t < 31 && a > -1e29f) ? expf(a - mx) : 0.f;
        if (t < 31) w[nl][t] = ee;
        float den = ee;
#pragma unroll
        for (int o = 16; o > 0; o >>= 1) den += __shfl_xor_sync(0xFFFFFFFFu, den, o);
        if (t == 0) invden[nl] = 1.f / den;
    }
    __syncthreads();
    float acc = 0.f;
#pragma unroll
    for (int e = 0; e < 31; e++) acc += w[nl][e] * xlin[(size_t)srcv[nl][e] * 64 + t];
    agg[(size_t)v * 64 + t] = acc * invden[nl] + bias[t];
}

// ---------------- column stats over 32768 rows x 64 cols ----------------
__global__ void colstat_part_kernel(const float* __restrict__ x, float* __restrict__ part) {
    int c = threadIdx.x & 63, rl = threadIdx.x >> 6;
    int base = blockIdx.x * 256;
    float s = 0.f, sq = 0.f;
    for (int r = rl; r < 256; r += 4) {
        float v = x[(size_t)(base + r) * 64 + c];
        s += v; sq += v * v;
    }
    __shared__ float ss[4][64], sqv[4][64];
    ss[rl][c] = s; sqv[rl][c] = sq;
    __syncthreads();
    if (rl == 0) {
        part[blockIdx.x * 128 + c]      = ss[0][c] + ss[1][c] + ss[2][c] + ss[3][c];
        part[blockIdx.x * 128 + 64 + c] = sqv[0][c] + sqv[1][c] + sqv[2][c] + sqv[3][c];
    }
}
__global__ void colstat_fin_kernel(const float* __restrict__ part, float* __restrict__ stats) {
    int c = threadIdx.x;
    float s = 0.f, sq = 0.f;
    for (int bk = 0; bk < 128; bk++) { s += part[bk * 128 + c]; sq += part[bk * 128 + 64 + c]; }
    float m = s * (1.f / 32768.f);
    float var = sq * (1.f / 32768.f) - m * m;
    stats[c]      = m;
    stats[64 + c] = rsqrtf(var + EPS);
}

// ---------------- gnn BN + relu + mul embeds, fused tb column-stat partials ----------------
__global__ void gnnbn_mul_stat_kernel(const float* __restrict__ agg, const float* __restrict__ stats,
                                      const float* __restrict__ g, const float* __restrict__ b,
                                      const float* __restrict__ embeds, float* __restrict__ tb,
                                      float* __restrict__ part) {
    int c = threadIdx.x & 63, rl = threadIdx.x >> 6;
    int base = blockIdx.x * 256;
    float mm = stats[c], rs = stats[64 + c], gg = g[c], bb = b[c];
    float s = 0.f, sq = 0.f;
    for (int r = rl; r < 256; r += 4) {
        int row = base + r;
        float h = (agg[(size_t)row * 64 + c] - mm) * rs * gg + bb;
        h = fmaxf(h, 0.f);
        float val = h * embeds[(row & 127) * 64 + c];
        tb[(size_t)row * 64 + c] = val;
        s += val; sq += val * val;
    }
    __shared__ float ss[4][64], sqv[4][64];
    ss[rl][c] = s; sqv[rl][c] = sq;
    __syncthreads();
    if (rl == 0) {
        part[blockIdx.x * 128 + c]      = ss[0][c] + ss[1][c] + ss[2][c] + ss[3][c];
        part[blockIdx.x * 128 + 64 + c] = sqv[0][c] + sqv[1][c] + sqv[2][c] + sqv[3][c];
    }
}

// ---------------- out BN + relu + output projection ----------------
__global__ void frcst_kernel(const float* __restrict__ tb, const float* __restrict__ stats,
                             const float* __restrict__ g, const float* __restrict__ b,
                             const float* __restrict__ outW, const float* __restrict__ outb,
                             float* __restrict__ out) {
    int t = threadIdx.x;
    int warp = t >> 5, lane = t & 31;
    int v = blockIdx.x * 8 + warp;
    float acc = 0.f;
#pragma unroll
    for (int d = lane; d < 64; d += 32) {
        float val = (tb[(size_t)v * 64 + d] - stats[d]) * stats[64 + d] * g[d] + b[d];
        val = fmaxf(val, 0.f);
        acc += val * outW[d];
    }
#pragma unroll
    for (int o = 16; o > 0; o >>= 1) acc += __shfl_xor_sync(0xFFFFFFFFu, acc, o);
    if (lane == 0) out[v] = acc + outb[0];
}

// ---------------- launch ----------------
extern "C" void kernel_launch(void* const* d_in, const int* in_sizes, int n_in,
                              void* d_out, int out_size) {
    const float* data      = (const float*)d_in[0];
    const float* enc_W     = (const float*)d_in[3];
    const float* enc_b     = (const float*)d_in[4];
    const float* enc_bn_g  = (const float*)d_in[5];
    const float* enc_bn_b  = (const float*)d_in[6];
    const float* dec_W     = (const float*)d_in[7];
    const float* dec_b     = (const float*)d_in[8];
    const float* dec_bn_g  = (const float*)d_in[9];
    const float* dec_bn_b  = (const float*)d_in[10];
    const float* emb_tab   = (const float*)d_in[11];
    const float* gru_Wih   = (const float*)d_in[12];
    const float* gru_bih   = (const float*)d_in[14];
    const float* gru_bhh   = (const float*)d_in[15];
    const float* gnn_lin_W = (const float*)d_in[16];
    const float* att_i     = (const float*)d_in[17];
    const float* att_j     = (const float*)d_in[18];
    const float* att_em_i  = (const float*)d_in[19];
    const float* att_em_j  = (const float*)d_in[20];
    const float* gnn_bias  = (const float*)d_in[21];
    const float* gnn_bn_g  = (const float*)d_in[22];
    const float* gnn_bn_b  = (const float*)d_in[23];
    const float* bn_out_g  = (const float*)d_in[24];
    const float* bn_out_b  = (const float*)d_in[25];
    const float* out_W     = (const float*)d_in[26];
    const float* out_b     = (const float*)d_in[27];

    float* out = (float*)d_out;
    float* o_frcst  = out;
    float* o_recon  = o_frcst  + 32768;
    float* o_z      = o_recon  + 524288;
    float* o_encf0  = o_z      + 524288;
    float* o_decf0  = o_encf0  + 524288;
    float* o_allemb = o_decf0  + 524288;
    float* o_y      = o_allemb + 2097152;
    float* o_rhos   = o_y      + 32768;
    float* o_rhohat = o_rhos   + 2048;

    float *p_lin, *p_bnp, *p_csp, *p_emb, *p_ei, *p_ej, *p_xlin, *p_si, *p_sj,
          *p_agg, *p_tb, *p_part, *p_st1, *p_st2;
    unsigned short *p_ab, *p_wb;
    int   *p_topk;
    cudaGetSymbolAddress((void**)&p_lin,  d_lin);
    cudaGetSymbolAddress((void**)&p_ab,   d_abuf);
    cudaGetSymbolAddress((void**)&p_wb,   d_wbuf4);
    cudaGetSymbolAddress((void**)&p_bnp,  d_bnp);
    cudaGetSymbolAddress((void**)&p_csp,  d_cspart);
    cudaGetSymbolAddress((void**)&p_emb,  d_embeds);
    cudaGetSymbolAddress((void**)&p_ei,   d_ei);
    cudaGetSymbolAddress((void**)&p_ej,   d_ej);
    cudaGetSymbolAddress((void**)&p_topk, d_topkbuf);
    cudaGetSymbolAddress((void**)&p_xlin, d_xlin);
    cudaGetSymbolAddress((void**)&p_si,   d_si);
    cudaGetSymbolAddress((void**)&p_sj,   d_sj);
    cudaGetSymbolAddress((void**)&p_agg,  d_agg);
    cudaGetSymbolAddress((void**)&p_tb,   d_tb);
    cudaGetSymbolAddress((void**)&p_part, d_part);
    cudaGetSymbolAddress((void**)&p_st1,  d_stats1);
    cudaGetSymbolAddress((void**)&p_st2,  d_stats2);
    unsigned short* p_w[4] = { p_wb, p_wb + (size_t)NW * 4096, p_wb + 2 * (size_t)NW * 4096,
                               p_wb + 3 * (size_t)NW * 4096 };
    const float* Wsrc[4] = { enc_W, enc_W + (size_t)NW * NW, dec_W, dec_W + (size_t)NW * NW };

    const int GEMM_SMEM = 3 * 2 * STAGE_SH * 2;   // 104448 bytes
    cudaFuncSetAttribute(gemm_mma_kernel, cudaFuncAttributeMaxDynamicSharedMemorySize, GEMM_SMEM);

    dim3 ggrid(32, 4);
    dim3 csgrid(8, 16);

    // ---- streams / events: created ONCE; reused on capture call ----
    static cudaStream_t s1 = nullptr, s2 = nullptr;
    static cudaEvent_t eFork, eW[4], eZ, eSide;
    static bool inited = false;
    if (!inited) {
        cudaStreamCreateWithFlags(&s1, cudaStreamNonBlocking);
        cudaStreamCreateWithFlags(&s2, cudaStreamNonBlocking);
        cudaEventCreateWithFlags(&eFork, cudaEventDisableTiming);
        for (int i = 0; i < 4; i++) cudaEventCreateWithFlags(&eW[i], cudaEventDisableTiming);
        cudaEventCreateWithFlags(&eZ, cudaEventDisableTiming);
        cudaEventCreateWithFlags(&eSide, cudaEventDisableTiming);
        inited = true;
    }

    cudaEventRecord(eFork, 0);
    cudaStreamWaitEvent(s1, eFork, 0);
    cudaStreamWaitEvent(s2, eFork, 0);

    // ---- s1: weight conversions (each gated separately) ----
    for (int i = 0; i < 4; i++) {
        conv_hilo_kernel<<<4096, 256, 0, s1>>>(Wsrc[i], p_w[i]);
        cudaEventRecord(eW[i], s1);
    }

    // ---- s2: GRU -> topk -> misc (independent of encoder) ----
    gru_kernel<<<128, 192, 0, s2>>>(emb_tab, gru_Wih, gru_bih, gru_bhh, att_em_i, att_em_j,
                                    p_emb, p_ei, p_ej);
    topk_kernel<<<1, 128, 0, s2>>>(p_emb, p_topk);
    misc_kernel<<<8192, 256, 0, s2>>>(p_emb, o_allemb, o_y, o_rhos);

    // ---- main: encoder ----
    conv_hilo_kernel<<<512, 256>>>(data, p_ab);
    cudaStreamWaitEvent(0, eW[0], 0);
    gemm_mma_kernel<<<ggrid, 512, GEMM_SMEM>>>(p_ab, p_w[0], enc_b, p_lin, p_bnp);
    bn_apply_sig_kernel<1><<<512, 256>>>(p_lin, p_bnp, enc_bn_g, enc_bn_b, o_encf0, p_ab);
    cudaStreamWaitEvent(0, eW[1], 0);
    gemm_mma_kernel<<<ggrid, 512, GEMM_SMEM>>>(p_ab, p_w[1], enc_b + NW, p_lin, p_bnp);
    bn_apply_sig_kernel<1><<<512, 256>>>(p_lin, p_bnp, enc_bn_g + NW, enc_bn_b + NW, o_z, p_ab);
    cudaEventRecord(eZ, 0);

    // ---- s2: after z ready — colsum + full GNN chain, parallel with decoder ----
    cudaStreamWaitEvent(s2, eZ, 0);
    colsum_part_kernel<<<csgrid, 256, 0, s2>>>(o_z, p_csp);
    colsum_fin_kernel<<<8, 256, 0, s2>>>(p_csp, o_rhohat);
    xlin_score_kernel<<<4096, 256, 0, s2>>>(o_z, gnn_lin_W, att_i, att_j, p_ei, p_ej,
                                            p_xlin, p_si, p_sj);
    attn_kernel<<<8192, 256, 0, s2>>>(p_xlin, p_si, p_sj, p_topk, gnn_bias, p_agg);
    colstat_part_kernel<<<128, 256, 0, s2>>>(p_agg, p_part);
    colstat_fin_kernel<<<1, 64, 0, s2>>>(p_part, p_st1);
    gnnbn_mul_stat_kernel<<<128, 256, 0, s2>>>(p_agg, p_st1, gnn_bn_g, gnn_bn_b, p_emb, p_tb, p_part);
    colstat_fin_kernel<<<1, 64, 0, s2>>>(p_part, p_st2);
    frcst_kernel<<<4096, 256, 0, s2>>>(p_tb, p_st2, bn_out_g, bn_out_b, out_W, out_b, o_frcst);
    cudaEventRecord(eSide, s2);

    // ---- main: decoder ----
    cudaStreamWaitEvent(0, eW[2], 0);
    gemm_mma_kernel<<<ggrid, 512, GEMM_SMEM>>>(p_ab, p_w[2], dec_b, p_lin, p_bnp);
    bn_apply_sig_kernel<1><<<512, 256>>>(p_lin, p_bnp, dec_bn_g, dec_bn_b, o_decf0, p_ab);
    cudaStreamWaitEvent(0, eW[3], 0);
    gemm_mma_kernel<<<ggrid, 512, GEMM_SMEM>>>(p_ab, p_w[3], dec_b + NW, p_lin, p_bnp);
    bn_apply_sig_kernel<0><<<512, 256>>>(p_lin, p_bnp, dec_bn_g + NW, dec_bn_b + NW, o_recon, nullptr);

    // ---- join side branch back to origin stream ----
    cudaStreamWaitEvent(0, eSide, 0);
}

// round 14
// speedup vs baseline: 1.1940x; 1.1940x over previous
#include <cuda_runtime.h>
#include <cuda_bf16.h>
#include <cstdint>

// ---------------- constants ----------------
#define Bb 256
#define Nn 128
#define Ww 16
#define Dd 64
#define TOPK 30
#define NW 2048               // N*W
#define BN_NODES 32768        // B*N
#define EPS 1e-5f

// hi/lo dedup layout: each bf16 buffer is [rows x 4096]: cols 0-2047 = hi, 2048-4095 = lo.
// Logical K = 6144 with region mapping: (A hi, W hi), (A lo, W hi), (A hi, W lo).

// ---------------- scratch ----------------
__device__ float d_lin[Bb * NW];
__device__ float d_cp[2][Bb * NW];          // split-K partials (4 MB)
__device__ __align__(16) unsigned short d_abuf[Bb * 4096];
__device__ __align__(16) unsigned short d_wbuf4[4][NW * 4096];   // 64 MB: one per layer
__device__ float d_bnp[2 * 16 * NW];        // BN partials: sums[16][NW], sqs[16][NW]
__device__ float d_cspart[16 * NW];
__device__ float d_embeds[Nn * Dd];
__device__ float d_ei[Nn];
__device__ float d_ej[Nn];
__device__ int   d_topkbuf[Nn * TOPK];
__device__ float d_xlin[BN_NODES * Dd];
__device__ float d_si[BN_NODES];
__device__ float d_sj[BN_NODES];
__device__ float d_agg[BN_NODES * Dd];
__device__ float d_tb[BN_NODES * Dd];
__device__ float d_part[128 * 128];
__device__ float d_stats1[128];
__device__ float d_stats2[128];

__device__ __forceinline__ uint32_t smem_u32(const void* p) {
    uint32_t a;
    asm("{ .reg .u64 t; cvta.to.shared.u64 t, %1; cvt.u32.u64 %0, t; }" : "=r"(a) : "l"(p));
    return a;
}
__device__ __forceinline__ void ldsm_x4(uint32_t& r0, uint32_t& r1, uint32_t& r2, uint32_t& r3,
                                        uint32_t addr) {
    asm volatile("ldmatrix.sync.aligned.m8n8.x4.shared.b16 {%0,%1,%2,%3}, [%4];"
                 : "=r"(r0), "=r"(r1), "=r"(r2), "=r"(r3) : "r"(addr));
}

// ---------------- hi/lo helpers ----------------
__device__ __forceinline__ void f4_to_hilo(float4 x, uint2& hv, uint2& lv) {
    __nv_bfloat16 h0 = __float2bfloat16_rn(x.x), h1 = __float2bfloat16_rn(x.y);
    __nv_bfloat16 h2 = __float2bfloat16_rn(x.z), h3 = __float2bfloat16_rn(x.w);
    __nv_bfloat16 l0 = __float2bfloat16_rn(x.x - __bfloat162float(h0));
    __nv_bfloat16 l1 = __float2bfloat16_rn(x.y - __bfloat162float(h1));
    __nv_bfloat16 l2 = __float2bfloat16_rn(x.z - __bfloat162float(h2));
    __nv_bfloat16 l3 = __float2bfloat16_rn(x.w - __bfloat162float(h3));
    __nv_bfloat162 hA = __nv_bfloat162(h0, h1), hB = __nv_bfloat162(h2, h3);
    __nv_bfloat162 lA = __nv_bfloat162(l0, l1), lB = __nv_bfloat162(l2, l3);
    hv.x = *(uint32_t*)&hA; hv.y = *(uint32_t*)&hB;
    lv.x = *(uint32_t*)&lA; lv.y = *(uint32_t*)&lB;
}

// ---------------- convert: X fp32 [rows x 2048] -> Y bf16 [rows x 4096] = [hi|lo] ----------------
__global__ void conv_hilo_kernel(const float* __restrict__ X, unsigned short* __restrict__ Y) {
    int idx = blockIdx.x * 256 + threadIdx.x;
    int m = idx >> 9, k4 = (idx & 511) << 2;
    float4 x = *(const float4*)(X + (size_t)m * NW + k4);
    uint2 hv, lv;
    f4_to_hilo(x, hv, lv);
    unsigned short* yr = Y + (size_t)m * 4096 + k4;
    *(uint2*)yr = hv;
    *(uint2*)(yr + 2048) = lv;
}

// ---------------- HMMA GEMM, split-K=2 ----------------
// CTA tile 64x64, 256 threads (8 warps 4m x 2n, warp tile 16x32),
// k-step 64, 3-stage pipeline, 54 KB smem -> 2 CTAs/SM. grid (32, 4, 2).
#define SMST 72
#define STAGE_SH (64 * SMST)
__global__ void __launch_bounds__(256, 2)
gemm_mma_kernel(const unsigned short* __restrict__ Ag, const unsigned short* __restrict__ Wg,
                float* __restrict__ Cp) {
    extern __shared__ unsigned short sh[];
    int tid = threadIdx.x, wid = tid >> 5, lane = tid & 31;
    int wm = wid >> 1, wn = wid & 1;
    int m0 = blockIdx.y * 64, n0 = blockIdx.x * 64;
    int kz = blockIdx.z * 3072;             // split-K half
    int g = lane >> 2, t = lane & 3;

    float acc[4][4];
#pragma unroll
    for (int ni = 0; ni < 4; ni++)
#pragma unroll
        for (int q = 0; q < 4; q++) acc[ni][q] = 0.f;

    // loader: per stage per matrix: 64 rows x 8 chunks(16B) = 512 chunks; 256 thr x 2 iters
    auto load_stage = [&](int st, int s) {
        int kb = kz + s * 64;
        int r = kb >> 11, koff = kb & 2047;
        int aoff = (r == 1) ? 2048 : 0;
        int woff = (r == 2) ? 2048 : 0;
        unsigned short* as = sh + st * 2 * STAGE_SH;
        unsigned short* bs = as + STAGE_SH;
#pragma unroll
        for (int i = 0; i < 2; i++) {
            int id = i * 256 + tid;
            int row = id >> 3, c16 = (id & 7) * 8;
            uint32_t dA = smem_u32(as + row * SMST + c16);
            const void* sA = Ag + (size_t)(m0 + row) * 4096 + aoff + koff + c16;
            asm volatile("cp.async.cg.shared.global [%0], [%1], 16;" :: "r"(dA), "l"(sA));
            uint32_t dB = smem_u32(bs + row * SMST + c16);
            const void* sB = Wg + (size_t)(n0 + row) * 4096 + woff + koff + c16;
            asm volatile("cp.async.cg.shared.global [%0], [%1], 16;" :: "r"(dB), "l"(sB));
        }
        asm volatile("cp.async.commit_group;" ::: "memory");
    };

    load_stage(0, 0);
    load_stage(1, 1);

    const int NS = 48;   // 3072 / 64
    int arow = wm * 16 + (lane & 15);
    int acol8 = (lane >> 4) << 3;
    int bnrow0 = wn * 32 + ((lane >> 4) << 3) + (lane & 7);
    int bcol8 = ((lane >> 3) & 1) << 3;
    for (int s = 0; s < NS; s++) {
        if (s < NS - 1) asm volatile("cp.async.wait_group 1;" ::: "memory");
        else            asm volatile("cp.async.wait_group 0;" ::: "memory");
        __syncthreads();
        if (s + 2 < NS) load_stage((s + 2) % 3, s + 2);

        const unsigned short* as = sh + (s % 3) * 2 * STAGE_SH;
        const unsigned short* bs = as + STAGE_SH;
#pragma unroll
        for (int ks = 0; ks < 4; ks++) {
            int kc = ks * 16;
            uint32_t a0, a1, a2, a3;
            ldsm_x4(a0, a1, a2, a3, smem_u32(as + arow * SMST + kc + acol8));
            uint32_t b0, b1, b2, b3, b4, b5, b6, b7;
            ldsm_x4(b0, b1, b2, b3, smem_u32(bs + bnrow0 * SMST + kc + bcol8));
            ldsm_x4(b4, b5, b6, b7, smem_u32(bs + (bnrow0 + 16) * SMST + kc + bcol8));
#define MMA(ACC, B0, B1) \
            asm volatile("mma.sync.aligned.m16n8k16.row.col.f32.bf16.bf16.f32 " \
                         "{%0,%1,%2,%3}, {%4,%5,%6,%7}, {%8,%9}, {%0,%1,%2,%3};" \
                         : "+f"(ACC[0]), "+f"(ACC[1]), "+f"(ACC[2]), "+f"(ACC[3]) \
                         : "r"(a0), "r"(a1), "r"(a2), "r"(a3), "r"(B0), "r"(B1))
            MMA(acc[0], b0, b1);
            MMA(acc[1], b2, b3);
            MMA(acc[2], b4, b5);
            MMA(acc[3], b6, b7);
#undef MMA
        }
    }

    // ---- epilogue: store raw partials ----
    float* Co = Cp + (size_t)blockIdx.z * Bb * NW;
    int row = m0 + wm * 16 + g;
#pragma unroll
    for (int ni = 0; ni < 4; ni++) {
        int col = n0 + wn * 32 + ni * 8 + 2 * t;
        float* c = acc[ni];
        float2 o0; o0.x = c[0]; o0.y = c[1];
        float2 o1; o1.x = c[2]; o1.y = c[3];
        *(float2*)(Co + (size_t)row * NW + col) = o0;
        *(float2*)(Co + (size_t)(row + 8) * NW + col) = o1;
    }
}

// ---------------- reduce split-K + bias, fused BN column partials (16 row chunks) ----------
__global__ void reduce_stats_kernel(const float* __restrict__ Cp, const float* __restrict__ bias,
                                    float* __restrict__ C, float* __restrict__ bnp) {
    int c = blockIdx.x * 256 + threadIdx.x;
    int r0 = blockIdx.y * 16;
    float bi = bias[c];
    float s = 0.f, sq = 0.f;
#pragma unroll
    for (int r = 0; r < 16; r++) {
        size_t off = (size_t)(r0 + r) * NW + c;
        float v = Cp[off] + Cp[(size_t)Bb * NW + off] + bi;
        C[off] = v;
        s += v; sq += v * v;
    }
    bnp[blockIdx.y * NW + c]            = s;
    bnp[16 * NW + blockIdx.y * NW + c]  = sq;
}

// ---------------- BN apply + sigmoid with inline 16-partial finalize; optional bf16 emit ------
template <int EMIT>
__global__ void bn_apply_sig_kernel(const float* __restrict__ X, const float* __restrict__ bnp,
                                    const float* __restrict__ g, const float* __restrict__ b,
                                    float* __restrict__ Y, unsigned short* __restrict__ Ab) {
    int idx4 = blockIdx.x * blockDim.x + threadIdx.x;
    int m = idx4 >> 9, c4 = (idx4 & 511) << 2;
    float4 x  = *(const float4*)(X + (size_t)idx4 * 4);
    float4 gg = *(const float4*)(g + c4);
    float4 bb = *(const float4*)(b + c4);
    float4 sv = make_float4(0.f, 0.f, 0.f, 0.f), qv = make_float4(0.f, 0.f, 0.f, 0.f);
#pragma unroll
    for (int i = 0; i < 16; i++) {
        float4 si = *(const float4*)(bnp + i * NW + c4);
        float4 qi = *(const float4*)(bnp + 16 * NW + i * NW + c4);
        sv.x += si.x; sv.y += si.y; sv.z += si.z; sv.w += si.w;
        qv.x += qi.x; qv.y += qi.y; qv.z += qi.z; qv.w += qi.w;
    }
    float4 mm, rs;
    mm.x = sv.x * (1.f / 256.f); mm.y = sv.y * (1.f / 256.f);
    mm.z = sv.z * (1.f / 256.f); mm.w = sv.w * (1.f / 256.f);
    rs.x = rsqrtf(qv.x * (1.f / 256.f) - mm.x * mm.x + EPS);
    rs.y = rsqrtf(qv.y * (1.f / 256.f) - mm.y * mm.y + EPS);
    rs.z = rsqrtf(qv.z * (1.f / 256.f) - mm.z * mm.z + EPS);
    rs.w = rsqrtf(qv.w * (1.f / 256.f) - mm.w * mm.w + EPS);
    float4 o;
    o.x = 1.f / (1.f + expf(-((x.x - mm.x) * rs.x * gg.x + bb.x)));
    o.y = 1.f / (1.f + expf(-((x.y - mm.y) * rs.y * gg.y + bb.y)));
    o.z = 1.f / (1.f + expf(-((x.z - mm.z) * rs.z * gg.z + bb.z)));
    o.w = 1.f / (1.f + expf(-((x.w - mm.w) * rs.w * gg.w + bb.w)));
    *(float4*)(Y + (size_t)idx4 * 4) = o;
    if (EMIT) {
        uint2 hv, lv;
        f4_to_hilo(o, hv, lv);
        unsigned short* yr = Ab + (size_t)m * 4096 + c4;
        *(uint2*)yr = hv;
        *(uint2*)(yr + 2048) = lv;
    }
}

// ---------------- rho_hat = column sums of z ----------------
__global__ void colsum_part_kernel(const float* __restrict__ X, float* __restrict__ part) {
    int c = blockIdx.x * 256 + threadIdx.x;
    int r0 = blockIdx.y * 16;
    float s = 0.f;
#pragma unroll
    for (int r = 0; r < 16; r++) s += X[(size_t)(r0 + r) * NW + c];
    part[blockIdx.y * NW + c] = s;
}
__global__ void colsum_fin_kernel(const float* __restrict__ part, float* __restrict__ out) {
    int c = blockIdx.x * 256 + threadIdx.x;
    float s = 0.f;
#pragma unroll
    for (int i = 0; i < 16; i++) s += part[i * NW + c];
    out[c] = s;
}

// ---------------- misc: all_emb + y_process + rhos ----------------
__device__ __forceinline__ uint32_t rotl32(uint32_t x, uint32_t r) { return (x << r) | (x >> (32 - r)); }
__device__ __forceinline__ float tf_uniform(uint32_t bits) {
    uint32_t ub = (bits >> 9) | 0x3F800000u;
    float u = __uint_as_float(ub) - 1.0f;
    float v = u * (0.01f - 1e-5f) + 1e-5f;
    return fmaxf(1e-5f, v);
}
__global__ void misc_kernel(const float* __restrict__ embeds, float* __restrict__ allemb,
                            float* __restrict__ yp, float* __restrict__ rhos) {
    int idx = blockIdx.x * 256 + threadIdx.x;
    allemb[idx] = embeds[idx & 8191];
    if (idx < BN_NODES) yp[idx] = (float)(idx >> 13);
    if (idx < 2048) {
        const uint32_t k0 = 0u, k1 = 42u;
        uint32_t ks[3] = {k0, k1, k0 ^ k1 ^ 0x1BD11BDAu};
        uint32_t x0 = 0u + ks[0];
        uint32_t x1 = (uint32_t)idx + ks[1];
        const uint32_t rot[2][4] = {{13u, 15u, 26u, 6u}, {17u, 29u, 16u, 24u}};
#pragma unroll
        for (int r = 0; r < 5; r++) {
#pragma unroll
            for (int j = 0; j < 4; j++) {
                x0 += x1;
                x1 = rotl32(x1, rot[r & 1][j]);
                x1 ^= x0;
            }
            x0 += ks[(r + 1) % 3];
            x1 += ks[(r + 2) % 3] + (uint32_t)(r + 1);
        }
        rhos[idx] = tf_uniform(x0 ^ x1);
    }
}

// ---------------- GRU embeddings ----------------
__global__ void gru_kernel(const float* __restrict__ emb, const float* __restrict__ Wih,
                           const float* __restrict__ bih, const float* __restrict__ bhh,
                           const float* __restrict__ att_em_i, const float* __restrict__ att_em_j,
                           float* __restrict__ embeds, float* __restrict__ ei, float* __restrict__ ej) {
    int node = blockIdx.x;
    int proc = node >> 5;
    int t = threadIdx.x;
    int dir = t / 96, g = t % 96;
    __shared__ float x[64], gi[2][96], xn[64];
    if (t < 64) x[t] = emb[(size_t)node * 64 + t];
    __syncthreads();
    for (int l = 0; l < 3; l++) {
        {
            size_t base = (((size_t)proc * 3 + l) * 2 + dir) * 96 + g;
            const float* Wr = Wih + base * 64;
            float s = bih[base];
#pragma unroll
            for (int k = 0; k < 64; k++) s += Wr[k] * x[k];
            gi[dir][g] = s;
        }
        __syncthreads();
        if (g < 32) {
            int j = g;
            size_t bb = (((size_t)proc * 3 + l) * 2 + dir) * 96;
            float rh = bhh[bb + j], zh = bhh[bb + 32 + j], nh = bhh[bb + 64 + j];
            float r  = 1.f / (1.f + expf(-(gi[dir][j] + rh)));
            float zz = 1.f / (1.f + expf(-(gi[dir][32 + j] + zh)));
            float n  = tanhf(gi[dir][64 + j] + r * nh);
            xn[dir * 32 + j] = (1.f - zz) * n;
        }
        __syncthreads();
        if (t < 64) x[t] = xn[t];
        __syncthreads();
    }
    if (t < 64) embeds[(size_t)node * 64 + t] = x[t];
    if (t == 0) {
        float si = 0.f, sj = 0.f;
        for (int d = 0; d < 64; d++) { si += x[d] * att_em_i[d]; sj += x[d] * att_em_j[d]; }
        ei[node] = si; ej[node] = sj;
    }
}

// ---------------- cosine-sim top-k ----------------
__global__ void topk_kernel(const float* __restrict__ embeds, int* __restrict__ topk) {
    __shared__ float en[128][65];
    int t = threadIdx.x;
    float row[64]; float s = 0.f;
    for (int d = 0; d < 64; d++) { float v = embeds[t * 64 + d]; row[d] = v; s += v * v; }
    float nrm = sqrtf(s);
    for (int d = 0; d < 64; d++) en[t][d] = row[d] / nrm;
    __syncthreads();
    float sim[128];
    for (int j = 0; j < 128; j++) {
        float acc = 0.f;
        for (int d = 0; d < 64; d++) acc += en[t][d] * en[j][d];
        sim[j] = acc;
    }
    for (int k = 0; k < TOPK; k++) {
        float best = -1e38f; int bi = 0;
        for (int j = 0; j < 128; j++) if (sim[j] > best) { best = sim[j]; bi = j; }
        topk[t * TOPK + k] = bi;
        sim[bi] = -1e38f;
    }
}

// ---------------- x_lin + per-node attention scores ----------------
__global__ void xlin_score_kernel(const float* __restrict__ z, const float* __restrict__ W,
                                  const float* __restrict__ att_i, const float* __restrict__ att_j,
                                  const float* __restrict__ ei, const float* __restrict__ ej,
                                  float* __restrict__ xlin, float* __restrict__ si, float* __restrict__ sj) {
    __shared__ float Ws[64][17];
    __shared__ float ai[64], aj[64];
    int t = threadIdx.x;
    if (t < 64) { ai[t] = att_i[t]; aj[t] = att_j[t]; }
    for (int idx = t; idx < 1024; idx += 256) Ws[idx >> 4][idx & 15] = W[idx];
    __syncthreads();
    int warp = t >> 5, lane = t & 31;
    int v = blockIdx.x * 8 + warp;
    float zr[16];
#pragma unroll
    for (int k = 0; k < 16; k++) zr[k] = z[(size_t)v * 16 + k];
    int d0 = lane, d1 = lane + 32;
    float x0 = 0.f, x1 = 0.f;
#pragma unroll
    for (int k = 0; k < 16; k++) { x0 += zr[k] * Ws[d0][k]; x1 += zr[k] * Ws[d1][k]; }
    xlin[(size_t)v * 64 + d0] = x0;
    xlin[(size_t)v * 64 + d1] = x1;
    float pi = x0 * ai[d0] + x1 * ai[d1];
    float pj = x0 * aj[d0] + x1 * aj[d1];
#pragma unroll
    for (int o = 16; o > 0; o >>= 1) {
        pi += __shfl_xor_sync(0xFFFFFFFFu, pi, o);
        pj += __shfl_xor_sync(0xFFFFFFFFu, pj, o);
    }
    if (lane == 0) {
        int i = v & 127;
        si[v] = pi + ei[i];
        sj[v] = pj + ej[i];
    }
}

// ---------------- GAT attention aggregation ----------------
__global__ void attn_kernel(const float* __restrict__ xlin, const float* __restrict__ si,
                            const float* __restrict__ sj, const int* __restrict__ topk,
                            const float* __restrict__ bias, float* __restrict__ agg) {
    int nl = threadIdx.x >> 6;
    int t  = threadIdx.x & 63;
    int v = blockIdx.x * 4 + nl;
    int i = v & 127, b = v >> 7;
    __shared__ float w[4][32];
    __shared__ int   srcv[4][31];
    __shared__ float invden[4];
    if (t < 32) {
        float a = -3e38f;
        if (t < 31) {
            int s, valid;
            if (t < 30) { s = topk[i * TOPK + t]; valid = (s != i); }
            else        { s = i; valid = 1; }
            int sv = (b << 7) + s;
            srcv[nl][t] = sv;
            float raw = si[v] + sj[sv];
            raw = raw > 0.f ? raw : 0.2f * raw;
            a = valid ? raw : -1e30f;
        }
        float mx = a;
#pragma unroll
        for (int o = 16; o > 0; o >>= 1) mx = fmaxf(mx, __shfl_xor_sync(0xFFFFFFFFu, mx, o));
        float ee = (t < 31 && a > -1e29f) ? expf(a - mx) : 0.f;
        if (t < 31) w[nl][t] = ee;
        float den = ee;
#pragma unroll
        for (int o = 16; o > 0; o >>= 1) den += __shfl_xor_sync(0xFFFFFFFFu, den, o);
        if (t == 0) invden[nl] = 1.f / den;
    }
    __syncthreads();
    float acc = 0.f;
#pragma unroll
    for (int e = 0; e < 31; e++) acc += w[nl][e] * xlin[(size_t)srcv[nl][e] * 64 + t];
    agg[(size_t)v * 64 + t] = acc * invden[nl] + bias[t];
}

// ---------------- column stats over 32768 rows x 64 cols ----------------
__global__ void colstat_part_kernel(const float* __restrict__ x, float* __restrict__ part) {
    int c = threadIdx.x & 63, rl = threadIdx.x >> 6;
    int base = blockIdx.x * 256;
    float s = 0.f, sq = 0.f;
    for (int r = rl; r < 256; r += 4) {
        float v = x[(size_t)(base + r) * 64 + c];
        s += v; sq += v * v;
    }
    __shared__ float ss[4][64], sqv[4][64];
    ss[rl][c] = s; sqv[rl][c] = sq;
    __syncthreads();
    if (rl == 0) {
        part[blockIdx.x * 128 + c]      = ss[0][c] + ss[1][c] + ss[2][c] + ss[3][c];
        part[blockIdx.x * 128 + 64 + c] = sqv[0][c] + sqv[1][c] + sqv[2][c] + sqv[3][c];
    }
}
__global__ void colstat_fin_kernel(const float* __restrict__ part, float* __restrict__ stats) {
    int c = threadIdx.x;
    float s = 0.f, sq = 0.f;
    for (int bk = 0; bk < 128; bk++) { s += part[bk * 128 + c]; sq += part[bk * 128 + 64 + c]; }
    float m = s * (1.f / 32768.f);
    float var = sq * (1.f / 32768.f) - m * m;
    stats[c]      = m;
    stats[64 + c] = rsqrtf(var + EPS);
}

// ---------------- gnn BN + relu + mul embeds, fused tb column-stat partials ----------------
__global__ void gnnbn_mul_stat_kernel(const float* __restrict__ agg, const float* __restrict__ stats,
                                      const float* __restrict__ g, const float* __restrict__ b,
                                      const float* __restrict__ embeds, float* __restrict__ tb,
                                      float* __restrict__ part) {
    int c = threadIdx.x & 63, rl = threadIdx.x >> 6;
    int base = blockIdx.x * 256;
    float mm = stats[c], rs = stats[64 + c], gg = g[c], bb = b[c];
    float s = 0.f, sq = 0.f;
    for (int r = rl; r < 256; r += 4) {
        int row = base + r;
        float h = (agg[(size_t)row * 64 + c] - mm) * rs * gg + bb;
        h = fmaxf(h, 0.f);
        float val = h * embeds[(row & 127) * 64 + c];
        tb[(size_t)row * 64 + c] = val;
        s += val; sq += val * val;
    }
    __shared__ float ss[4][64], sqv[4][64];
    ss[rl][c] = s; sqv[rl][c] = sq;
    __syncthreads();
    if (rl == 0) {
        part[blockIdx.x * 128 + c]      = ss[0][c] + ss[1][c] + ss[2][c] + ss[3][c];
        part[blockIdx.x * 128 + 64 + c] = sqv[0][c] + sqv[1][c] + sqv[2][c] + sqv[3][c];
    }
}

// ---------------- out BN + relu + output projection ----------------
__global__ void frcst_kernel(const float* __restrict__ tb, const float* __restrict__ stats,
                             const float* __restrict__ g, const float* __restrict__ b,
                             const float* __restrict__ outW, const float* __restrict__ outb,
                             float* __restrict__ out) {
    int t = threadIdx.x;
    int warp = t >> 5, lane = t & 31;
    int v = blockIdx.x * 8 + warp;
    float acc = 0.f;
#pragma unroll
    for (int d = lane; d < 64; d += 32) {
        float val = (tb[(size_t)v * 64 + d] - stats[d]) * stats[64 + d] * g[d] + b[d];
        val = fmaxf(val, 0.f);
        acc += val * outW[d];
    }
#pragma unroll
    for (int o = 16; o > 0; o >>= 1) acc += __shfl_xor_sync(0xFFFFFFFFu, acc, o);
    if (lane == 0) out[v] = acc + outb[0];
}

// ---------------- launch ----------------
extern "C" void kernel_launch(void* const* d_in, const int* in_sizes, int n_in,
                              void* d_out, int out_size) {
    const float* data      = (const float*)d_in[0];
    const float* enc_W     = (const float*)d_in[3];
    const float* enc_b     = (const float*)d_in[4];
    const float* enc_bn_g  = (const float*)d_in[5];
    const float* enc_bn_b  = (const float*)d_in[6];
    const float* dec_W     = (const float*)d_in[7];
    const float* dec_b     = (const float*)d_in[8];
    const float* dec_bn_g  = (const float*)d_in[9];
    const float* dec_bn_b  = (const float*)d_in[10];
    const float* emb_tab   = (const float*)d_in[11];
    const float* gru_Wih   = (const float*)d_in[12];
    const float* gru_bih   = (const float*)d_in[14];
    const float* gru_bhh   = (const float*)d_in[15];
    const float* gnn_lin_W = (const float*)d_in[16];
    const float* att_i     = (const float*)d_in[17];
    const float* att_j     = (const float*)d_in[18];
    const float* att_em_i  = (const float*)d_in[19];
    const float* att_em_j  = (const float*)d_in[20];
    const float* gnn_bias  = (const float*)d_in[21];
    const float* gnn_bn_g  = (const float*)d_in[22];
    const float* gnn_bn_b  = (const float*)d_in[23];
    const float* bn_out_g  = (const float*)d_in[24];
    const float* bn_out_b  = (const float*)d_in[25];
    const float* out_W     = (const float*)d_in[26];
    const float* out_b     = (const float*)d_in[27];

    float* out = (float*)d_out;
    float* o_frcst  = out;
    float* o_recon  = o_frcst  + 32768;
    float* o_z      = o_recon  + 524288;
    float* o_encf0  = o_z      + 524288;
    float* o_decf0  = o_encf0  + 524288;
    float* o_allemb = o_decf0  + 524288;
    float* o_y      = o_allemb + 2097152;
    float* o_rhos   = o_y      + 32768;
    float* o_rhohat = o_rhos   + 2048;

    float *p_lin, *p_cp, *p_bnp, *p_csp, *p_emb, *p_ei, *p_ej, *p_xlin, *p_si, *p_sj,
          *p_agg, *p_tb, *p_part, *p_st1, *p_st2;
    unsigned short *p_ab, *p_wb;
    int   *p_topk;
    cudaGetSymbolAddress((void**)&p_lin,  d_lin);
    cudaGetSymbolAddress((void**)&p_cp,   d_cp);
    cudaGetSymbolAddress((void**)&p_ab,   d_abuf);
    cudaGetSymbolAddress((void**)&p_wb,   d_wbuf4);
    cudaGetSymbolAddress((void**)&p_bnp,  d_bnp);
    cudaGetSymbolAddress((void**)&p_csp,  d_cspart);
    cudaGetSymbolAddress((void**)&p_emb,  d_embeds);
    cudaGetSymbolAddress((void**)&p_ei,   d_ei);
    cudaGetSymbolAddress((void**)&p_ej,   d_ej);
    cudaGetSymbolAddress((void**)&p_topk, d_topkbuf);
    cudaGetSymbolAddress((void**)&p_xlin, d_xlin);
    cudaGetSymbolAddress((void**)&p_si,   d_si);
    cudaGetSymbolAddress((void**)&p_sj,   d_sj);
    cudaGetSymbolAddress((void**)&p_agg,  d_agg);
    cudaGetSymbolAddress((void**)&p_tb,   d_tb);
    cudaGetSymbolAddress((void**)&p_part, d_part);
    cudaGetSymbolAddress((void**)&p_st1,  d_stats1);
    cudaGetSymbolAddress((void**)&p_st2,  d_stats2);
    unsigned short* p_w[4] = { p_wb, p_wb + (size_t)NW * 4096, p_wb + 2 * (size_t)NW * 4096,
                               p_wb + 3 * (size_t)NW * 4096 };
    const float* Wsrc[4] = { enc_W, enc_W + (size_t)NW * NW, dec_W, dec_W + (size_t)NW * NW };

    const int GEMM_SMEM = 3 * 2 * STAGE_SH * 2;   // 55296 bytes -> 2 CTAs/SM
    cudaFuncSetAttribute(gemm_mma_kernel, cudaFuncAttributeMaxDynamicSharedMemorySize, GEMM_SMEM);

    dim3 ggrid(32, 4, 2);
    dim3 rsgrid(8, 16);
    dim3 csgrid(8, 16);

    // ---- streams / events: created ONCE; reused on capture call ----
    static cudaStream_t s1 = nullptr, s2 = nullptr;
    static cudaEvent_t eFork, eW[4], eZ, eSide;
    static bool inited = false;
    if (!inited) {
        cudaStreamCreateWithFlags(&s1, cudaStreamNonBlocking);
        cudaStreamCreateWithFlags(&s2, cudaStreamNonBlocking);
        cudaEventCreateWithFlags(&eFork, cudaEventDisableTiming);
        for (int i = 0; i < 4; i++) cudaEventCreateWithFlags(&eW[i], cudaEventDisableTiming);
        cudaEventCreateWithFlags(&eZ, cudaEventDisableTiming);
        cudaEventCreateWithFlags(&eSide, cudaEventDisableTiming);
        inited = true;
    }

    cudaEventRecord(eFork, 0);
    cudaStreamWaitEvent(s1, eFork, 0);
    cudaStreamWaitEvent(s2, eFork, 0);

    // ---- s1: weight conversions (each gated separately) ----
    for (int i = 0; i < 4; i++) {
        conv_hilo_kernel<<<4096, 256, 0, s1>>>(Wsrc[i], p_w[i]);
        cudaEventRecord(eW[i], s1);
    }

    // ---- s2: GRU -> topk -> misc (independent of encoder) ----
    gru_kernel<<<128, 192, 0, s2>>>(emb_tab, gru_Wih, gru_bih, gru_bhh, att_em_i, att_em_j,
                                    p_emb, p_ei, p_ej);
    topk_kernel<<<1, 128, 0, s2>>>(p_emb, p_topk);
    misc_kernel<<<8192, 256, 0, s2>>>(p_emb, o_allemb, o_y, o_rhos);

    // ---- main: encoder ----
    conv_hilo_kernel<<<512, 256>>>(data, p_ab);
    cudaStreamWaitEvent(0, eW[0], 0);
    gemm_mma_kernel<<<ggrid, 256, GEMM_SMEM>>>(p_ab, p_w[0], p_cp);
    reduce_stats_kernel<<<rsgrid, 256>>>(p_cp, enc_b, p_lin, p_bnp);
    bn_apply_sig_kernel<1><<<512, 256>>>(p_lin, p_bnp, enc_bn_g, enc_bn_b, o_encf0, p_ab);
    cudaStreamWaitEvent(0, eW[1], 0);
    gemm_mma_kernel<<<ggrid, 256, GEMM_SMEM>>>(p_ab, p_w[1], p_cp);
    reduce_stats_kernel<<<rsgrid, 256>>>(p_cp, enc_b + NW, p_lin, p_bnp);
    bn_apply_sig_kernel<1><<<512, 256>>>(p_lin, p_bnp, enc_bn_g + NW, enc_bn_b + NW, o_z, p_ab);
    cudaEventRecord(eZ, 0);

    // ---- s2: after z ready — colsum + full GNN chain, parallel with decoder ----
    cudaStreamWaitEvent(s2, eZ, 0);
    colsum_part_kernel<<<csgrid, 256, 0, s2>>>(o_z, p_csp);
    colsum_fin_kernel<<<8, 256, 0, s2>>>(p_csp, o_rhohat);
    xlin_score_kernel<<<4096, 256, 0, s2>>>(o_z, gnn_lin_W, att_i, att_j, p_ei, p_ej,
                                            p_xlin, p_si, p_sj);
    attn_kernel<<<8192, 256, 0, s2>>>(p_xlin, p_si, p_sj, p_topk, gnn_bias, p_agg);
    colstat_part_kernel<<<128, 256, 0, s2>>>(p_agg, p_part);
    colstat_fin_kernel<<<1, 64, 0, s2>>>(p_part, p_st1);
    gnnbn_mul_stat_kernel<<<128, 256, 0, s2>>>(p_agg, p_st1, gnn_bn_g, gnn_bn_b, p_emb, p_tb, p_part);
    colstat_fin_kernel<<<1, 64, 0, s2>>>(p_part, p_st2);
    frcst_kernel<<<4096, 256, 0, s2>>>(p_tb, p_st2, bn_out_g, bn_out_b, out_W, out_b, o_frcst);
    cudaEventRecord(eSide, s2);

    // ---- main: decoder ----
    cudaStreamWaitEvent(0, eW[2], 0);
    gemm_mma_kernel<<<ggrid, 256, GEMM_SMEM>>>(p_ab, p_w[2], p_cp);
    reduce_stats_kernel<<<rsgrid, 256>>>(p_cp, dec_b, p_lin, p_bnp);
    bn_apply_sig_kernel<1><<<512, 256>>>(p_lin, p_bnp, dec_bn_g, dec_bn_b, o_decf0, p_ab);
    cudaStreamWaitEvent(0, eW[3], 0);
    gemm_mma_kernel<<<ggrid, 256, GEMM_SMEM>>>(p_ab, p_w[3], p_cp);
    reduce_stats_kernel<<<rsgrid, 256>>>(p_cp, dec_b + NW, p_lin, p_bnp);
    bn_apply_sig_kernel<0><<<512, 256>>>(p_lin, p_bnp, dec_bn_g + NW, dec_bn_b + NW, o_recon, nullptr);

    // ---- join side branch back to origin stream ----
    cudaStreamWaitEvent(0, eSide, 0);
}

// round 15
// speedup vs baseline: 1.2771x; 1.0695x over previous
#include <cuda_runtime.h>
#include <cuda_bf16.h>
#include <cstdint>

// ---------------- constants ----------------
#define Bb 256
#define Nn 128
#define Ww 16
#define Dd 64
#define TOPK 30
#define NW 2048               // N*W
#define BN_NODES 32768        // B*N
#define EPS 1e-5f

// hi/lo dedup layout: each bf16 buffer is [rows x 4096]: cols 0-2047 = hi, 2048-4095 = lo.
// Logical K = 6144 with region mapping: (A hi, W hi), (A lo, W hi), (A hi, W lo).

// ---------------- scratch ----------------
__device__ float d_lin[Bb * NW];
__device__ float d_cp[4][Bb * NW];          // split-K partials (8 MB)
__device__ __align__(16) unsigned short d_abuf[Bb * 4096];
__device__ __align__(16) unsigned short d_wbuf4[4][NW * 4096];   // 64 MB: one per layer
__device__ float d_bnp[2 * 16 * NW];        // BN partials: sums[16][NW], sqs[16][NW]
__device__ float d_cspart[16 * NW];
__device__ float d_embeds[Nn * Dd];
__device__ float d_ei[Nn];
__device__ float d_ej[Nn];
__device__ int   d_topkbuf[Nn * TOPK];
__device__ float d_xlin[BN_NODES * Dd];
__device__ float d_si[BN_NODES];
__device__ float d_sj[BN_NODES];
__device__ float d_agg[BN_NODES * Dd];
__device__ float d_tb[BN_NODES * Dd];
__device__ float d_part[128 * 128];
__device__ float d_stats1[128];
__device__ float d_stats2[128];

__device__ __forceinline__ uint32_t smem_u32(const void* p) {
    uint32_t a;
    asm("{ .reg .u64 t; cvta.to.shared.u64 t, %1; cvt.u32.u64 %0, t; }" : "=r"(a) : "l"(p));
    return a;
}
__device__ __forceinline__ void ldsm_x4(uint32_t& r0, uint32_t& r1, uint32_t& r2, uint32_t& r3,
                                        uint32_t addr) {
    asm volatile("ldmatrix.sync.aligned.m8n8.x4.shared.b16 {%0,%1,%2,%3}, [%4];"
                 : "=r"(r0), "=r"(r1), "=r"(r2), "=r"(r3) : "r"(addr));
}

// ---------------- hi/lo helpers ----------------
__device__ __forceinline__ void f4_to_hilo(float4 x, uint2& hv, uint2& lv) {
    __nv_bfloat16 h0 = __float2bfloat16_rn(x.x), h1 = __float2bfloat16_rn(x.y);
    __nv_bfloat16 h2 = __float2bfloat16_rn(x.z), h3 = __float2bfloat16_rn(x.w);
    __nv_bfloat16 l0 = __float2bfloat16_rn(x.x - __bfloat162float(h0));
    __nv_bfloat16 l1 = __float2bfloat16_rn(x.y - __bfloat162float(h1));
    __nv_bfloat16 l2 = __float2bfloat16_rn(x.z - __bfloat162float(h2));
    __nv_bfloat16 l3 = __float2bfloat16_rn(x.w - __bfloat162float(h3));
    __nv_bfloat162 hA = __nv_bfloat162(h0, h1), hB = __nv_bfloat162(h2, h3);
    __nv_bfloat162 lA = __nv_bfloat162(l0, l1), lB = __nv_bfloat162(l2, l3);
    hv.x = *(uint32_t*)&hA; hv.y = *(uint32_t*)&hB;
    lv.x = *(uint32_t*)&lA; lv.y = *(uint32_t*)&lB;
}

// ---------------- convert: X fp32 [rows x 2048] -> Y bf16 [rows x 4096] = [hi|lo] ----------------
__global__ void conv_hilo_kernel(const float* __restrict__ X, unsigned short* __restrict__ Y) {
    int idx = blockIdx.x * 256 + threadIdx.x;
    int m = idx >> 9, k4 = (idx & 511) << 2;
    float4 x = *(const float4*)(X + (size_t)m * NW + k4);
    uint2 hv, lv;
    f4_to_hilo(x, hv, lv);
    unsigned short* yr = Y + (size_t)m * 4096 + k4;
    *(uint2*)yr = hv;
    *(uint2*)(yr + 2048) = lv;
}

// ---------------- HMMA GEMM, split-K=4 ----------------
// CTA tile 64x64, 128 threads (4 warps 2m x 2n, warp tile 32x32),
// k-step 64, 3-stage pipeline, 54 KB smem -> up to 4 CTAs/SM. grid (32, 4, 4).
#define SMST 72
#define STAGE_SH (64 * SMST)
__global__ void __launch_bounds__(128, 4)
gemm_mma_kernel(const unsigned short* __restrict__ Ag, const unsigned short* __restrict__ Wg,
                float* __restrict__ Cp) {
    extern __shared__ unsigned short sh[];
    int tid = threadIdx.x, wid = tid >> 5, lane = tid & 31;
    int wm = wid >> 1, wn = wid & 1;
    int m0 = blockIdx.y * 64, n0 = blockIdx.x * 64;
    int kz = blockIdx.z * 1536;             // split-K quarter
    int g = lane >> 2, t = lane & 3;

    float acc[2][4][4];
#pragma unroll
    for (int mi = 0; mi < 2; mi++)
#pragma unroll
        for (int ni = 0; ni < 4; ni++)
#pragma unroll
            for (int q = 0; q < 4; q++) acc[mi][ni][q] = 0.f;

    // loader: per stage per matrix: 64 rows x 8 chunks(16B) = 512 chunks; 128 thr x 4 iters
    auto load_stage = [&](int st, int s) {
        int kb = kz + s * 64;
        int r = kb >> 11, koff = kb & 2047;
        int aoff = (r == 1) ? 2048 : 0;
        int woff = (r == 2) ? 2048 : 0;
        unsigned short* as = sh + st * 2 * STAGE_SH;
        unsigned short* bs = as + STAGE_SH;
#pragma unroll
        for (int i = 0; i < 4; i++) {
            int id = i * 128 + tid;
            int row = id >> 3, c16 = (id & 7) * 8;
            uint32_t dA = smem_u32(as + row * SMST + c16);
            const void* sA = Ag + (size_t)(m0 + row) * 4096 + aoff + koff + c16;
            asm volatile("cp.async.cg.shared.global [%0], [%1], 16;" :: "r"(dA), "l"(sA));
            uint32_t dB = smem_u32(bs + row * SMST + c16);
            const void* sB = Wg + (size_t)(n0 + row) * 4096 + woff + koff + c16;
            asm volatile("cp.async.cg.shared.global [%0], [%1], 16;" :: "r"(dB), "l"(sB));
        }
        asm volatile("cp.async.commit_group;" ::: "memory");
    };

    load_stage(0, 0);
    load_stage(1, 1);

    const int NS = 24;   // 1536 / 64
    int arow = wm * 32 + (lane & 15);
    int acol8 = (lane >> 4) << 3;
    int bnrow0 = wn * 32 + ((lane >> 4) << 3) + (lane & 7);
    int bcol8 = ((lane >> 3) & 1) << 3;
    for (int s = 0; s < NS; s++) {
        if (s < NS - 1) asm volatile("cp.async.wait_group 1;" ::: "memory");
        else            asm volatile("cp.async.wait_group 0;" ::: "memory");
        __syncthreads();
        if (s + 2 < NS) load_stage((s + 2) % 3, s + 2);

        const unsigned short* as = sh + (s % 3) * 2 * STAGE_SH;
        const unsigned short* bs = as + STAGE_SH;
#pragma unroll
        for (int ks = 0; ks < 4; ks++) {
            int kc = ks * 16;
            uint32_t a0, a1, a2, a3, a4, a5, a6, a7;
            ldsm_x4(a0, a1, a2, a3, smem_u32(as + arow * SMST + kc + acol8));
            ldsm_x4(a4, a5, a6, a7, smem_u32(as + (arow + 16) * SMST + kc + acol8));
            uint32_t b0, b1, b2, b3, b4, b5, b6, b7;
            ldsm_x4(b0, b1, b2, b3, smem_u32(bs + bnrow0 * SMST + kc + bcol8));
            ldsm_x4(b4, b5, b6, b7, smem_u32(bs + (bnrow0 + 16) * SMST + kc + bcol8));
#define MMA(ACC, A0, A1, A2, A3, B0, B1) \
            asm volatile("mma.sync.aligned.m16n8k16.row.col.f32.bf16.bf16.f32 " \
                         "{%0,%1,%2,%3}, {%4,%5,%6,%7}, {%8,%9}, {%0,%1,%2,%3};" \
                         : "+f"(ACC[0]), "+f"(ACC[1]), "+f"(ACC[2]), "+f"(ACC[3]) \
                         : "r"(A0), "r"(A1), "r"(A2), "r"(A3), "r"(B0), "r"(B1))
            MMA(acc[0][0], a0, a1, a2, a3, b0, b1);
            MMA(acc[0][1], a0, a1, a2, a3, b2, b3);
            MMA(acc[0][2], a0, a1, a2, a3, b4, b5);
            MMA(acc[0][3], a0, a1, a2, a3, b6, b7);
            MMA(acc[1][0], a4, a5, a6, a7, b0, b1);
            MMA(acc[1][1], a4, a5, a6, a7, b2, b3);
            MMA(acc[1][2], a4, a5, a6, a7, b4, b5);
            MMA(acc[1][3], a4, a5, a6, a7, b6, b7);
#undef MMA
        }
    }

    // ---- epilogue: store raw partials ----
    float* Co = Cp + (size_t)blockIdx.z * Bb * NW;
#pragma unroll
    for (int mi = 0; mi < 2; mi++) {
        int row = m0 + wm * 32 + mi * 16 + g;
#pragma unroll
        for (int ni = 0; ni < 4; ni++) {
            int col = n0 + wn * 32 + ni * 8 + 2 * t;
            float* c = acc[mi][ni];
            float2 o0; o0.x = c[0]; o0.y = c[1];
            float2 o1; o1.x = c[2]; o1.y = c[3];
            *(float2*)(Co + (size_t)row * NW + col) = o0;
            *(float2*)(Co + (size_t)(row + 8) * NW + col) = o1;
        }
    }
}

// ---------------- reduce split-K(4) + bias, fused BN column partials (16 row chunks) ----------
__global__ void reduce_stats_kernel(const float* __restrict__ Cp, const float* __restrict__ bias,
                                    float* __restrict__ C, float* __restrict__ bnp) {
    int c = blockIdx.x * 256 + threadIdx.x;
    int r0 = blockIdx.y * 16;
    float bi = bias[c];
    float s = 0.f, sq = 0.f;
#pragma unroll
    for (int r = 0; r < 16; r++) {
        size_t off = (size_t)(r0 + r) * NW + c;
        float v = Cp[off] + Cp[(size_t)Bb * NW + off]
                + Cp[2 * (size_t)Bb * NW + off] + Cp[3 * (size_t)Bb * NW + off] + bi;
        C[off] = v;
        s += v; sq += v * v;
    }
    bnp[blockIdx.y * NW + c]            = s;
    bnp[16 * NW + blockIdx.y * NW + c]  = sq;
}

// ---------------- BN apply + sigmoid with inline 16-partial finalize; optional bf16 emit ------
template <int EMIT>
__global__ void bn_apply_sig_kernel(const float* __restrict__ X, const float* __restrict__ bnp,
                                    const float* __restrict__ g, const float* __restrict__ b,
                                    float* __restrict__ Y, unsigned short* __restrict__ Ab) {
    int idx4 = blockIdx.x * blockDim.x + threadIdx.x;
    int m = idx4 >> 9, c4 = (idx4 & 511) << 2;
    float4 x  = *(const float4*)(X + (size_t)idx4 * 4);
    float4 gg = *(const float4*)(g + c4);
    float4 bb = *(const float4*)(b + c4);
    float4 sv = make_float4(0.f, 0.f, 0.f, 0.f), qv = make_float4(0.f, 0.f, 0.f, 0.f);
#pragma unroll
    for (int i = 0; i < 16; i++) {
        float4 si = *(const float4*)(bnp + i * NW + c4);
        float4 qi = *(const float4*)(bnp + 16 * NW + i * NW + c4);
        sv.x += si.x; sv.y += si.y; sv.z += si.z; sv.w += si.w;
        qv.x += qi.x; qv.y += qi.y; qv.z += qi.z; qv.w += qi.w;
    }
    float4 mm, rs;
    mm.x = sv.x * (1.f / 256.f); mm.y = sv.y * (1.f / 256.f);
    mm.z = sv.z * (1.f / 256.f); mm.w = sv.w * (1.f / 256.f);
    rs.x = rsqrtf(qv.x * (1.f / 256.f) - mm.x * mm.x + EPS);
    rs.y = rsqrtf(qv.y * (1.f / 256.f) - mm.y * mm.y + EPS);
    rs.z = rsqrtf(qv.z * (1.f / 256.f) - mm.z * mm.z + EPS);
    rs.w = rsqrtf(qv.w * (1.f / 256.f) - mm.w * mm.w + EPS);
    float4 o;
    o.x = 1.f / (1.f + expf(-((x.x - mm.x) * rs.x * gg.x + bb.x)));
    o.y = 1.f / (1.f + expf(-((x.y - mm.y) * rs.y * gg.y + bb.y)));
    o.z = 1.f / (1.f + expf(-((x.z - mm.z) * rs.z * gg.z + bb.z)));
    o.w = 1.f / (1.f + expf(-((x.w - mm.w) * rs.w * gg.w + bb.w)));
    *(float4*)(Y + (size_t)idx4 * 4) = o;
    if (EMIT) {
        uint2 hv, lv;
        f4_to_hilo(o, hv, lv);
        unsigned short* yr = Ab + (size_t)m * 4096 + c4;
        *(uint2*)yr = hv;
        *(uint2*)(yr + 2048) = lv;
    }
}

// ---------------- rho_hat = column sums of z ----------------
__global__ void colsum_part_kernel(const float* __restrict__ X, float* __restrict__ part) {
    int c = blockIdx.x * 256 + threadIdx.x;
    int r0 = blockIdx.y * 16;
    float s = 0.f;
#pragma unroll
    for (int r = 0; r < 16; r++) s += X[(size_t)(r0 + r) * NW + c];
    part[blockIdx.y * NW + c] = s;
}
__global__ void colsum_fin_kernel(const float* __restrict__ part, float* __restrict__ out) {
    int c = blockIdx.x * 256 + threadIdx.x;
    float s = 0.f;
#pragma unroll
    for (int i = 0; i < 16; i++) s += part[i * NW + c];
    out[c] = s;
}

// ---------------- misc: all_emb + y_process + rhos ----------------
__device__ __forceinline__ uint32_t rotl32(uint32_t x, uint32_t r) { return (x << r) | (x >> (32 - r)); }
__device__ __forceinline__ float tf_uniform(uint32_t bits) {
    uint32_t ub = (bits >> 9) | 0x3F800000u;
    float u = __uint_as_float(ub) - 1.0f;
    float v = u * (0.01f - 1e-5f) + 1e-5f;
    return fmaxf(1e-5f, v);
}
__global__ void misc_kernel(const float* __restrict__ embeds, float* __restrict__ allemb,
                            float* __restrict__ yp, float* __restrict__ rhos) {
    int idx = blockIdx.x * 256 + threadIdx.x;
    allemb[idx] = embeds[idx & 8191];
    if (idx < BN_NODES) yp[idx] = (float)(idx >> 13);
    if (idx < 2048) {
        const uint32_t k0 = 0u, k1 = 42u;
        uint32_t ks[3] = {k0, k1, k0 ^ k1 ^ 0x1BD11BDAu};
        uint32_t x0 = 0u + ks[0];
        uint32_t x1 = (uint32_t)idx + ks[1];
        const uint32_t rot[2][4] = {{13u, 15u, 26u, 6u}, {17u, 29u, 16u, 24u}};
#pragma unroll
        for (int r = 0; r < 5; r++) {
#pragma unroll
            for (int j = 0; j < 4; j++) {
                x0 += x1;
                x1 = rotl32(x1, rot[r & 1][j]);
                x1 ^= x0;
            }
            x0 += ks[(r + 1) % 3];
            x1 += ks[(r + 2) % 3] + (uint32_t)(r + 1);
        }
        rhos[idx] = tf_uniform(x0 ^ x1);
    }
}

// ---------------- GRU embeddings ----------------
__global__ void gru_kernel(const float* __restrict__ emb, const float* __restrict__ Wih,
                           const float* __restrict__ bih, const float* __restrict__ bhh,
                           const float* __restrict__ att_em_i, const float* __restrict__ att_em_j,
                           float* __restrict__ embeds, float* __restrict__ ei, float* __restrict__ ej) {
    int node = blockIdx.x;
    int proc = node >> 5;
    int t = threadIdx.x;
    int dir = t / 96, g = t % 96;
    __shared__ float x[64], gi[2][96], xn[64];
    if (t < 64) x[t] = emb[(size_t)node * 64 + t];
    __syncthreads();
    for (int l = 0; l < 3; l++) {
        {
            size_t base = (((size_t)proc * 3 + l) * 2 + dir) * 96 + g;
            const float* Wr = Wih + base * 64;
            float s = bih[base];
#pragma unroll
            for (int k = 0; k < 64; k++) s += Wr[k] * x[k];
            gi[dir][g] = s;
        }
        __syncthreads();
        if (g < 32) {
            int j = g;
            size_t bb = (((size_t)proc * 3 + l) * 2 + dir) * 96;
            float rh = bhh[bb + j], zh = bhh[bb + 32 + j], nh = bhh[bb + 64 + j];
            float r  = 1.f / (1.f + expf(-(gi[dir][j] + rh)));
            float zz = 1.f / (1.f + expf(-(gi[dir][32 + j] + zh)));
            float n  = tanhf(gi[dir][64 + j] + r * nh);
            xn[dir * 32 + j] = (1.f - zz) * n;
        }
        __syncthreads();
        if (t < 64) x[t] = xn[t];
        __syncthreads();
    }
    if (t < 64) embeds[(size_t)node * 64 + t] = x[t];
    if (t == 0) {
        float si = 0.f, sj = 0.f;
        for (int d = 0; d < 64; d++) { si += x[d] * att_em_i[d]; sj += x[d] * att_em_j[d]; }
        ei[node] = si; ej[node] = sj;
    }
}

// ---------------- cosine-sim top-k ----------------
__global__ void topk_kernel(const float* __restrict__ embeds, int* __restrict__ topk) {
    __shared__ float en[128][65];
    int t = threadIdx.x;
    float row[64]; float s = 0.f;
    for (int d = 0; d < 64; d++) { float v = embeds[t * 64 + d]; row[d] = v; s += v * v; }
    float nrm = sqrtf(s);
    for (int d = 0; d < 64; d++) en[t][d] = row[d] / nrm;
    __syncthreads();
    float sim[128];
    for (int j = 0; j < 128; j++) {
        float acc = 0.f;
        for (int d = 0; d < 64; d++) acc += en[t][d] * en[j][d];
        sim[j] = acc;
    }
    for (int k = 0; k < TOPK; k++) {
        float best = -1e38f; int bi = 0;
        for (int j = 0; j < 128; j++) if (sim[j] > best) { best = sim[j]; bi = j; }
        topk[t * TOPK + k] = bi;
        sim[bi] = -1e38f;
    }
}

// ---------------- x_lin + per-node attention scores ----------------
__global__ void xlin_score_kernel(const float* __restrict__ z, const float* __restrict__ W,
                                  const float* __restrict__ att_i, const float* __restrict__ att_j,
                                  const float* __restrict__ ei, const float* __restrict__ ej,
                                  float* __restrict__ xlin, float* __restrict__ si, float* __restrict__ sj) {
    __shared__ float Ws[64][17];
    __shared__ float ai[64], aj[64];
    int t = threadIdx.x;
    if (t < 64) { ai[t] = att_i[t]; aj[t] = att_j[t]; }
    for (int idx = t; idx < 1024; idx += 256) Ws[idx >> 4][idx & 15] = W[idx];
    __syncthreads();
    int warp = t >> 5, lane = t & 31;
    int v = blockIdx.x * 8 + warp;
    float zr[16];
#pragma unroll
    for (int k = 0; k < 16; k++) zr[k] = z[(size_t)v * 16 + k];
    int d0 = lane, d1 = lane + 32;
    float x0 = 0.f, x1 = 0.f;
#pragma unroll
    for (int k = 0; k < 16; k++) { x0 += zr[k] * Ws[d0][k]; x1 += zr[k] * Ws[d1][k]; }
    xlin[(size_t)v * 64 + d0] = x0;
    xlin[(size_t)v * 64 + d1] = x1;
    float pi = x0 * ai[d0] + x1 * ai[d1];
    float pj = x0 * aj[d0] + x1 * aj[d1];
#pragma unroll
    for (int o = 16; o > 0; o >>= 1) {
        pi += __shfl_xor_sync(0xFFFFFFFFu, pi, o);
        pj += __shfl_xor_sync(0xFFFFFFFFu, pj, o);
    }
    if (lane == 0) {
        int i = v & 127;
        si[v] = pi + ei[i];
        sj[v] = pj + ej[i];
    }
}

// ---------------- GAT attention aggregation ----------------
__global__ void attn_kernel(const float* __restrict__ xlin, const float* __restrict__ si,
                            const float* __restrict__ sj, const int* __restrict__ topk,
                            const float* __restrict__ bias, float* __restrict__ agg) {
    int nl = threadIdx.x >> 6;
    int t  = threadIdx.x & 63;
    int v = blockIdx.x * 4 + nl;
    int i = v & 127, b = v >> 7;
    __shared__ float w[4][32];
    __shared__ int   srcv[4][31];
    __shared__ float invden[4];
    if (t < 32) {
        float a = -3e38f;
        if (t < 31) {
            int s, valid;
            if (t < 30) { s = topk[i * TOPK + t]; valid = (s != i); }
            else        { s = i; valid = 1; }
            int sv = (b << 7) + s;
            srcv[nl][t] = sv;
            float raw = si[v] + sj[sv];
            raw = raw > 0.f ? raw : 0.2f * raw;
            a = valid ? raw : -1e30f;
        }
        float mx = a;
#pragma unroll
        for (int o = 16; o > 0; o >>= 1) mx = fmaxf(mx, __shfl_xor_sync(0xFFFFFFFFu, mx, o));
        float ee = (t < 31 && a > -1e29f) ? expf(a - mx) : 0.f;
        if (t < 31) w[nl][t] = ee;
        float den = ee;
#pragma unroll
        for (int o = 16; o > 0; o >>= 1) den += __shfl_xor_sync(0xFFFFFFFFu, den, o);
        if (t == 0) invden[nl] = 1.f / den;
    }
    __syncthreads();
    float acc = 0.f;
#pragma unroll
    for (int e = 0; e < 31; e++) acc += w[nl][e] * xlin[(size_t)srcv[nl][e] * 64 + t];
    agg[(size_t)v * 64 + t] = acc * invden[nl] + bias[t];
}

// ---------------- column stats over 32768 rows x 64 cols ----------------
__global__ void colstat_part_kernel(const float* __restrict__ x, float* __restrict__ part) {
    int c = threadIdx.x & 63, rl = threadIdx.x >> 6;
    int base = blockIdx.x * 256;
    float s = 0.f, sq = 0.f;
    for (int r = rl; r < 256; r += 4) {
        float v = x[(size_t)(base + r) * 64 + c];
        s += v; sq += v * v;
    }
    __shared__ float ss[4][64], sqv[4][64];
    ss[rl][c] = s; sqv[rl][c] = sq;
    __syncthreads();
    if (rl == 0) {
        part[blockIdx.x * 128 + c]      = ss[0][c] + ss[1][c] + ss[2][c] + ss[3][c];
        part[blockIdx.x * 128 + 64 + c] = sqv[0][c] + sqv[1][c] + sqv[2][c] + sqv[3][c];
    }
}
__global__ void colstat_fin_kernel(const float* __restrict__ part, float* __restrict__ stats) {
    int c = threadIdx.x;
    float s = 0.f, sq = 0.f;
    for (int bk = 0; bk < 128; bk++) { s += part[bk * 128 + c]; sq += part[bk * 128 + 64 + c]; }
    float m = s * (1.f / 32768.f);
    float var = sq * (1.f / 32768.f) - m * m;
    stats[c]      = m;
    stats[64 + c] = rsqrtf(var + EPS);
}

// ---------------- gnn BN + relu + mul embeds, fused tb column-stat partials ----------------
__global__ void gnnbn_mul_stat_kernel(const float* __restrict__ agg, const float* __restrict__ stats,
                                      const float* __restrict__ g, const float* __restrict__ b,
                                      const float* __restrict__ embeds, float* __restrict__ tb,
                                      float* __restrict__ part) {
    int c = threadIdx.x & 63, rl = threadIdx.x >> 6;
    int base = blockIdx.x * 256;
    float mm = stats[c], rs = stats[64 + c], gg = g[c], bb = b[c];
    float s = 0.f, sq = 0.f;
    for (int r = rl; r < 256; r += 4) {
        int row = base + r;
        float h = (agg[(size_t)row * 64 + c] - mm) * rs * gg + bb;
        h = fmaxf(h, 0.f);
        float val = h * embeds[(row & 127) * 64 + c];
        tb[(size_t)row * 64 + c] = val;
        s += val; sq += val * val;
    }
    __shared__ float ss[4][64], sqv[4][64];
    ss[rl][c] = s; sqv[rl][c] = sq;
    __syncthreads();
    if (rl == 0) {
        part[blockIdx.x * 128 + c]      = ss[0][c] + ss[1][c] + ss[2][c] + ss[3][c];
        part[blockIdx.x * 128 + 64 + c] = sqv[0][c] + sqv[1][c] + sqv[2][c] + sqv[3][c];
    }
}

// ---------------- out BN + relu + output projection ----------------
__global__ void frcst_kernel(const float* __restrict__ tb, const float* __restrict__ stats,
                             const float* __restrict__ g, const float* __restrict__ b,
                             const float* __restrict__ outW, const float* __restrict__ outb,
                             float* __restrict__ out) {
    int t = threadIdx.x;
    int warp = t >> 5, lane = t & 31;
    int v = blockIdx.x * 8 + warp;
    float acc = 0.f;
#pragma unroll
    for (int d = lane; d < 64; d += 32) {
        float val = (tb[(size_t)v * 64 + d] - stats[d]) * stats[64 + d] * g[d] + b[d];
        val = fmaxf(val, 0.f);
        acc += val * outW[d];
    }
#pragma unroll
    for (int o = 16; o > 0; o >>= 1) acc += __shfl_xor_sync(0xFFFFFFFFu, acc, o);
    if (lane == 0) out[v] = acc + outb[0];
}

// ---------------- launch ----------------
extern "C" void kernel_launch(void* const* d_in, const int* in_sizes, int n_in,
                              void* d_out, int out_size) {
    const float* data      = (const float*)d_in[0];
    const float* enc_W     = (const float*)d_in[3];
    const float* enc_b     = (const float*)d_in[4];
    const float* enc_bn_g  = (const float*)d_in[5];
    const float* enc_bn_b  = (const float*)d_in[6];
    const float* dec_W     = (const float*)d_in[7];
    const float* dec_b     = (const float*)d_in[8];
    const float* dec_bn_g  = (const float*)d_in[9];
    const float* dec_bn_b  = (const float*)d_in[10];
    const float* emb_tab   = (const float*)d_in[11];
    const float* gru_Wih   = (const float*)d_in[12];
    const float* gru_bih   = (const float*)d_in[14];
    const float* gru_bhh   = (const float*)d_in[15];
    const float* gnn_lin_W = (const float*)d_in[16];
    const float* att_i     = (const float*)d_in[17];
    const float* att_j     = (const float*)d_in[18];
    const float* att_em_i  = (const float*)d_in[19];
    const float* att_em_j  = (const float*)d_in[20];
    const float* gnn_bias  = (const float*)d_in[21];
    const float* gnn_bn_g  = (const float*)d_in[22];
    const float* gnn_bn_b  = (const float*)d_in[23];
    const float* bn_out_g  = (const float*)d_in[24];
    const float* bn_out_b  = (const float*)d_in[25];
    const float* out_W     = (const float*)d_in[26];
    const float* out_b     = (const float*)d_in[27];

    float* out = (float*)d_out;
    float* o_frcst  = out;
    float* o_recon  = o_frcst  + 32768;
    float* o_z      = o_recon  + 524288;
    float* o_encf0  = o_z      + 524288;
    float* o_decf0  = o_encf0  + 524288;
    float* o_allemb = o_decf0  + 524288;
    float* o_y      = o_allemb + 2097152;
    float* o_rhos   = o_y      + 32768;
    float* o_rhohat = o_rhos   + 2048;

    float *p_lin, *p_cp, *p_bnp, *p_csp, *p_emb, *p_ei, *p_ej, *p_xlin, *p_si, *p_sj,
          *p_agg, *p_tb, *p_part, *p_st1, *p_st2;
    unsigned short *p_ab, *p_wb;
    int   *p_topk;
    cudaGetSymbolAddress((void**)&p_lin,  d_lin);
    cudaGetSymbolAddress((void**)&p_cp,   d_cp);
    cudaGetSymbolAddress((void**)&p_ab,   d_abuf);
    cudaGetSymbolAddress((void**)&p_wb,   d_wbuf4);
    cudaGetSymbolAddress((void**)&p_bnp,  d_bnp);
    cudaGetSymbolAddress((void**)&p_csp,  d_cspart);
    cudaGetSymbolAddress((void**)&p_emb,  d_embeds);
    cudaGetSymbolAddress((void**)&p_ei,   d_ei);
    cudaGetSymbolAddress((void**)&p_ej,   d_ej);
    cudaGetSymbolAddress((void**)&p_topk, d_topkbuf);
    cudaGetSymbolAddress((void**)&p_xlin, d_xlin);
    cudaGetSymbolAddress((void**)&p_si,   d_si);
    cudaGetSymbolAddress((void**)&p_sj,   d_sj);
    cudaGetSymbolAddress((void**)&p_agg,  d_agg);
    cudaGetSymbolAddress((void**)&p_tb,   d_tb);
    cudaGetSymbolAddress((void**)&p_part, d_part);
    cudaGetSymbolAddress((void**)&p_st1,  d_stats1);
    cudaGetSymbolAddress((void**)&p_st2,  d_stats2);
    unsigned short* p_w[4] = { p_wb, p_wb + (size_t)NW * 4096, p_wb + 2 * (size_t)NW * 4096,
                               p_wb + 3 * (size_t)NW * 4096 };
    const float* Wsrc[4] = { enc_W, enc_W + (size_t)NW * NW, dec_W, dec_W + (size_t)NW * NW };

    const int GEMM_SMEM = 3 * 2 * STAGE_SH * 2;   // 55296 bytes
    cudaFuncSetAttribute(gemm_mma_kernel, cudaFuncAttributeMaxDynamicSharedMemorySize, GEMM_SMEM);

    dim3 ggrid(32, 4, 4);
    dim3 rsgrid(8, 16);
    dim3 csgrid(8, 16);

    // ---- streams / events: created ONCE; reused on capture call ----
    static cudaStream_t s1 = nullptr, s2 = nullptr;
    static cudaEvent_t eFork, eW[4], eZ, eSide;
    static bool inited = false;
    if (!inited) {
        cudaStreamCreateWithFlags(&s1, cudaStreamNonBlocking);
        cudaStreamCreateWithFlags(&s2, cudaStreamNonBlocking);
        cudaEventCreateWithFlags(&eFork, cudaEventDisableTiming);
        for (int i = 0; i < 4; i++) cudaEventCreateWithFlags(&eW[i], cudaEventDisableTiming);
        cudaEventCreateWithFlags(&eZ, cudaEventDisableTiming);
        cudaEventCreateWithFlags(&eSide, cudaEventDisableTiming);
        inited = true;
    }

    cudaEventRecord(eFork, 0);
    cudaStreamWaitEvent(s1, eFork, 0);
    cudaStreamWaitEvent(s2, eFork, 0);

    // ---- s1: weight conversions (each gated separately) ----
    for (int i = 0; i < 4; i++) {
        conv_hilo_kernel<<<4096, 256, 0, s1>>>(Wsrc[i], p_w[i]);
        cudaEventRecord(eW[i], s1);
    }

    // ---- s2: GRU -> topk -> misc (independent of encoder) ----
    gru_kernel<<<128, 192, 0, s2>>>(emb_tab, gru_Wih, gru_bih, gru_bhh, att_em_i, att_em_j,
                                    p_emb, p_ei, p_ej);
    topk_kernel<<<1, 128, 0, s2>>>(p_emb, p_topk);
    misc_kernel<<<8192, 256, 0, s2>>>(p_emb, o_allemb, o_y, o_rhos);

    // ---- main: encoder ----
    conv_hilo_kernel<<<512, 256>>>(data, p_ab);
    cudaStreamWaitEvent(0, eW[0], 0);
    gemm_mma_kernel<<<ggrid, 128, GEMM_SMEM>>>(p_ab, p_w[0], p_cp);
    reduce_stats_kernel<<<rsgrid, 256>>>(p_cp, enc_b, p_lin, p_bnp);
    bn_apply_sig_kernel<1><<<512, 256>>>(p_lin, p_bnp, enc_bn_g, enc_bn_b, o_encf0, p_ab);
    cudaStreamWaitEvent(0, eW[1], 0);
    gemm_mma_kernel<<<ggrid, 128, GEMM_SMEM>>>(p_ab, p_w[1], p_cp);
    reduce_stats_kernel<<<rsgrid, 256>>>(p_cp, enc_b + NW, p_lin, p_bnp);
    bn_apply_sig_kernel<1><<<512, 256>>>(p_lin, p_bnp, enc_bn_g + NW, enc_bn_b + NW, o_z, p_ab);
    cudaEventRecord(eZ, 0);

    // ---- s2: after z ready — colsum + full GNN chain, parallel with decoder ----
    cudaStreamWaitEvent(s2, eZ, 0);
    colsum_part_kernel<<<csgrid, 256, 0, s2>>>(o_z, p_csp);
    colsum_fin_kernel<<<8, 256, 0, s2>>>(p_csp, o_rhohat);
    xlin_score_kernel<<<4096, 256, 0, s2>>>(o_z, gnn_lin_W, att_i, att_j, p_ei, p_ej,
                                            p_xlin, p_si, p_sj);
    attn_kernel<<<8192, 256, 0, s2>>>(p_xlin, p_si, p_sj, p_topk, gnn_bias, p_agg);
    colstat_part_kernel<<<128, 256, 0, s2>>>(p_agg, p_part);
    colstat_fin_kernel<<<1, 64, 0, s2>>>(p_part, p_st1);
    gnnbn_mul_stat_kernel<<<128, 256, 0, s2>>>(p_agg, p_st1, gnn_bn_g, gnn_bn_b, p_emb, p_tb, p_part);
    colstat_fin_kernel<<<1, 64, 0, s2>>>(p_part, p_st2);
    frcst_kernel<<<4096, 256, 0, s2>>>(p_tb, p_st2, bn_out_g, bn_out_b, out_W, out_b, o_frcst);
    cudaEventRecord(eSide, s2);

    // ---- main: decoder ----
    cudaStreamWaitEvent(0, eW[2], 0);
    gemm_mma_kernel<<<ggrid, 128, GEMM_SMEM>>>(p_ab, p_w[2], p_cp);
    reduce_stats_kernel<<<rsgrid, 256>>>(p_cp, dec_b, p_lin, p_bnp);
    bn_apply_sig_kernel<1><<<512, 256>>>(p_lin, p_bnp, dec_bn_g, dec_bn_b, o_decf0, p_ab);
    cudaStreamWaitEvent(0, eW[3], 0);
    gemm_mma_kernel<<<ggrid, 128, GEMM_SMEM>>>(p_ab, p_w[3], p_cp);
    reduce_stats_kernel<<<rsgrid, 256>>>(p_cp, dec_b + NW, p_lin, p_bnp);
    bn_apply_sig_kernel<0><<<512, 256>>>(p_lin, p_bnp, dec_bn_g + NW, dec_bn_b + NW, o_recon, nullptr);

    // ---- join side branch back to origin stream ----
    cudaStreamWaitEvent(0, eSide, 0);
}

// round 17
// speedup vs baseline: 1.2873x; 1.0080x over previous
#include <cuda_runtime.h>
#include <cuda_bf16.h>
#include <cstdint>

// ---------------- constants ----------------
#define Bb 256
#define Nn 128
#define Ww 16
#define Dd 64
#define TOPK 30
#define NW 2048               // N*W
#define BN_NODES 32768        // B*N
#define EPS 1e-5f

// hi/lo dedup layout: each bf16 buffer is [rows x 4096]: cols 0-2047 = hi, 2048-4095 = lo.
// Logical K = 6144 with region mapping: (A hi, W hi), (A lo, W hi), (A hi, W lo).

// ---------------- scratch ----------------
__device__ float d_lin[Bb * NW];
__device__ int   d_flags[4 * 128];          // per-layer, per-tile split-K chain flags
__device__ __align__(16) unsigned short d_abuf[Bb * 4096];
__device__ __align__(16) unsigned short d_wbuf4[4][NW * 4096];   // 64 MB: one per layer
__device__ float d_bnp[2 * 4 * NW];         // BN partials: sums[4][NW], sqs[4][NW]
__device__ float d_cspart[16 * NW];
__device__ float d_embeds[Nn * Dd];
__device__ float d_ei[Nn];
__device__ float d_ej[Nn];
__device__ int   d_topkbuf[Nn * TOPK];
__device__ float d_xlin[BN_NODES * Dd];
__device__ float d_si[BN_NODES];
__device__ float d_sj[BN_NODES];
__device__ float d_agg[BN_NODES * Dd];
__device__ float d_tb[BN_NODES * Dd];
__device__ float d_part[128 * 128];
__device__ float d_stats1[128];
__device__ float d_stats2[128];

__device__ __forceinline__ uint32_t smem_u32(const void* p) {
    uint32_t a;
    asm("{ .reg .u64 t; cvta.to.shared.u64 t, %1; cvt.u32.u64 %0, t; }" : "=r"(a) : "l"(p));
    return a;
}
__device__ __forceinline__ void ldsm_x4(uint32_t& r0, uint32_t& r1, uint32_t& r2, uint32_t& r3,
                                        uint32_t addr) {
    asm volatile("ldmatrix.sync.aligned.m8n8.x4.shared.b16 {%0,%1,%2,%3}, [%4];"
                 : "=r"(r0), "=r"(r1), "=r"(r2), "=r"(r3) : "r"(addr));
}

// ---------------- hi/lo helpers ----------------
__device__ __forceinline__ void f4_to_hilo(float4 x, uint2& hv, uint2& lv) {
    __nv_bfloat16 h0 = __float2bfloat16_rn(x.x), h1 = __float2bfloat16_rn(x.y);
    __nv_bfloat16 h2 = __float2bfloat16_rn(x.z), h3 = __float2bfloat16_rn(x.w);
    __nv_bfloat16 l0 = __float2bfloat16_rn(x.x - __bfloat162float(h0));
    __nv_bfloat16 l1 = __float2bfloat16_rn(x.y - __bfloat162float(h1));
    __nv_bfloat16 l2 = __float2bfloat16_rn(x.z - __bfloat162float(h2));
    __nv_bfloat16 l3 = __float2bfloat16_rn(x.w - __bfloat162float(h3));
    __nv_bfloat162 hA = __nv_bfloat162(h0, h1), hB = __nv_bfloat162(h2, h3);
    __nv_bfloat162 lA = __nv_bfloat162(l0, l1), lB = __nv_bfloat162(l2, l3);
    hv.x = *(uint32_t*)&hA; hv.y = *(uint32_t*)&hB;
    lv.x = *(uint32_t*)&lA; lv.y = *(uint32_t*)&lB;
}

// ---------------- convert: X fp32 [rows x 2048] -> Y bf16 [rows x 4096] = [hi|lo] ----------------
// Optional: clears the split-K chain flags (A-conversion runs before all GEMMs in stream order).
__global__ void conv_hilo_kernel(const float* __restrict__ X, unsigned short* __restrict__ Y,
                                 int* __restrict__ flags) {
    int idx = blockIdx.x * 256 + threadIdx.x;
    if (flags && idx < 512) flags[idx] = 0;
    int m = idx >> 9, k4 = (idx & 511) << 2;
    float4 x = *(const float4*)(X + (size_t)m * NW + k4);
    uint2 hv, lv;
    f4_to_hilo(x, hv, lv);
    unsigned short* yr = Y + (size_t)m * 4096 + k4;
    *(uint2*)yr = hv;
    *(uint2*)(yr + 2048) = lv;
}

// ---------------- HMMA GEMM, split-K=4 with deterministic chained accumulation ----------------
// CTA tile 64x64, 128 threads (4 warps 2m x 2n, warp tile 32x32),
// k-step 64, 3-stage pipeline, 54 KB smem -> 4 CTAs/SM. grid (32, 4, 4).
// z=0 writes C; z=1,2 accumulate after flag z; z=3 adds bias, writes final C + BN partials.
#define SMST 72
#define STAGE_SH (64 * SMST)
__global__ void __launch_bounds__(128, 4)
gemm_mma_kernel(const unsigned short* __restrict__ Ag, const unsigned short* __restrict__ Wg,
                const float* __restrict__ bias, float* __restrict__ C,
                float* __restrict__ bnp, int* __restrict__ flags) {
    extern __shared__ unsigned short sh[];
    __shared__ float s_sum[2][64], s_sq[2][64];
    int tid = threadIdx.x, wid = tid >> 5, lane = tid & 31;
    int wm = wid >> 1, wn = wid & 1;
    int m0 = blockIdx.y * 64, n0 = blockIdx.x * 64;
    int z = blockIdx.z;
    int kz = z * 1536;
    int tile = blockIdx.y * 32 + blockIdx.x;
    int g = lane >> 2, t = lane & 3;

    float acc[2][4][4];
#pragma unroll
    for (int mi = 0; mi < 2; mi++)
#pragma unroll
        for (int ni = 0; ni < 4; ni++)
#pragma unroll
            for (int q = 0; q < 4; q++) acc[mi][ni][q] = 0.f;

    auto load_stage = [&](int st, int s) {
        int kb = kz + s * 64;
        int r = kb >> 11, koff = kb & 2047;
        int aoff = (r == 1) ? 2048 : 0;
        int woff = (r == 2) ? 2048 : 0;
        unsigned short* as = sh + st * 2 * STAGE_SH;
        unsigned short* bs = as + STAGE_SH;
#pragma unroll
        for (int i = 0; i < 4; i++) {
            int id = i * 128 + tid;
            int row = id >> 3, c16 = (id & 7) * 8;
            uint32_t dA = smem_u32(as + row * SMST + c16);
            const void* sA = Ag + (size_t)(m0 + row) * 4096 + aoff + koff + c16;
            asm volatile("cp.async.cg.shared.global [%0], [%1], 16;" :: "r"(dA), "l"(sA));
            uint32_t dB = smem_u32(bs + row * SMST + c16);
            const void* sB = Wg + (size_t)(n0 + row) * 4096 + woff + koff + c16;
            asm volatile("cp.async.cg.shared.global [%0], [%1], 16;" :: "r"(dB), "l"(sB));
        }
        asm volatile("cp.async.commit_group;" ::: "memory");
    };

    load_stage(0, 0);
    load_stage(1, 1);

    const int NS = 24;   // 1536 / 64
    int arow = wm * 32 + (lane & 15);
    int acol8 = (lane >> 4) << 3;
    int bnrow0 = wn * 32 + ((lane >> 4) << 3) + (lane & 7);
    int bcol8 = ((lane >> 3) & 1) << 3;
    for (int s = 0; s < NS; s++) {
        if (s < NS - 1) asm volatile("cp.async.wait_group 1;" ::: "memory");
        else            asm volatile("cp.async.wait_group 0;" ::: "memory");
        __syncthreads();
        if (s + 2 < NS) load_stage((s + 2) % 3, s + 2);

        const unsigned short* as = sh + (s % 3) * 2 * STAGE_SH;
        const unsigned short* bs = as + STAGE_SH;
#pragma unroll
        for (int ks = 0; ks < 4; ks++) {
            int kc = ks * 16;
            uint32_t a0, a1, a2, a3, a4, a5, a6, a7;
            ldsm_x4(a0, a1, a2, a3, smem_u32(as + arow * SMST + kc + acol8));
            ldsm_x4(a4, a5, a6, a7, smem_u32(as + (arow + 16) * SMST + kc + acol8));
            uint32_t b0, b1, b2, b3, b4, b5, b6, b7;
            ldsm_x4(b0, b1, b2, b3, smem_u32(bs + bnrow0 * SMST + kc + bcol8));
            ldsm_x4(b4, b5, b6, b7, smem_u32(bs + (bnrow0 + 16) * SMST + kc + bcol8));
#define MMA(ACC, A0, A1, A2, A3, B0, B1) \
            asm volatile("mma.sync.aligned.m16n8k16.row.col.f32.bf16.bf16.f32 " \
                         "{%0,%1,%2,%3}, {%4,%5,%6,%7}, {%8,%9}, {%0,%1,%2,%3};" \
                         : "+f"(ACC[0]), "+f"(ACC[1]), "+f"(ACC[2]), "+f"(ACC[3]) \
                         : "r"(A0), "r"(A1), "r"(A2), "r"(A3), "r"(B0), "r"(B1))
            MMA(acc[0][0], a0, a1, a2, a3, b0, b1);
            MMA(acc[0][1], a0, a1, a2, a3, b2, b3);
            MMA(acc[0][2], a0, a1, a2, a3, b4, b5);
            MMA(acc[0][3], a0, a1, a2, a3, b6, b7);
            MMA(acc[1][0], a4, a5, a6, a7, b0, b1);
            MMA(acc[1][1], a4, a5, a6, a7, b2, b3);
            MMA(acc[1][2], a4, a5, a6, a7, b4, b5);
            MMA(acc[1][3], a4, a5, a6, a7, b6, b7);
#undef MMA
        }
    }

    // ---- chained split-K epilogue ----
    if (z > 0) {
        if (tid == 0) { while (atomicAdd(&flags[tile], 0) < z) { } }
        __syncthreads();
        __threadfence();
    }
    if (z < 3) {
#pragma unroll
        for (int mi = 0; mi < 2; mi++) {
            int row = m0 + wm * 32 + mi * 16 + g;
#pragma unroll
            for (int ni = 0; ni < 4; ni++) {
                int col = n0 + wn * 32 + ni * 8 + 2 * t;
                float* c = acc[mi][ni];
                float2 o0, o1;
                if (z > 0) {
                    float2 p0 = *(float2*)(C + (size_t)row * NW + col);
                    float2 p1 = *(float2*)(C + (size_t)(row + 8) * NW + col);
                    o0.x = c[0] + p0.x; o0.y = c[1] + p0.y;
                    o1.x = c[2] + p1.x; o1.y = c[3] + p1.y;
                } else {
                    o0.x = c[0]; o0.y = c[1];
                    o1.x = c[2]; o1.y = c[3];
                }
                *(float2*)(C + (size_t)row * NW + col) = o0;
                *(float2*)(C + (size_t)(row + 8) * NW + col) = o1;
            }
        }
        __syncthreads();
        __threadfence();
        if (tid == 0) atomicExch(&flags[tile], z + 1);
    } else {
        float csum[8], csq[8];
#pragma unroll
        for (int q = 0; q < 8; q++) { csum[q] = 0.f; csq[q] = 0.f; }
#pragma unroll
        for (int mi = 0; mi < 2; mi++) {
            int row = m0 + wm * 32 + mi * 16 + g;
#pragma unroll
            for (int ni = 0; ni < 4; ni++) {
                int col = n0 + wn * 32 + ni * 8 + 2 * t;
                float2 bi = *(const float2*)(bias + col);
                float* c = acc[mi][ni];
                float2 p0 = *(float2*)(C + (size_t)row * NW + col);
                float2 p1 = *(float2*)(C + (size_t)(row + 8) * NW + col);
                float v0 = c[0] + p0.x + bi.x, v1 = c[1] + p0.y + bi.y;
                float v2 = c[2] + p1.x + bi.x, v3 = c[3] + p1.y + bi.y;
                float2 o0; o0.x = v0; o0.y = v1;
                float2 o1; o1.x = v2; o1.y = v3;
                *(float2*)(C + (size_t)row * NW + col) = o0;
                *(float2*)(C + (size_t)(row + 8) * NW + col) = o1;
                csum[ni * 2]     += v0 + v2;
                csum[ni * 2 + 1] += v1 + v3;
                csq[ni * 2]      += v0 * v0 + v2 * v2;
                csq[ni * 2 + 1]  += v1 * v1 + v3 * v3;
            }
        }
#pragma unroll
        for (int o = 4; o <= 16; o <<= 1) {
#pragma unroll
            for (int q = 0; q < 8; q++) {
                csum[q] += __shfl_xor_sync(0xFFFFFFFFu, csum[q], o);
                csq[q]  += __shfl_xor_sync(0xFFFFFFFFu, csq[q],  o);
            }
        }
        if (g == 0) {
#pragma unroll
            for (int ni = 0; ni < 4; ni++) {
                int cl = wn * 32 + ni * 8 + 2 * t;
                s_sum[wm][cl]     = csum[ni * 2];
                s_sum[wm][cl + 1] = csum[ni * 2 + 1];
                s_sq[wm][cl]      = csq[ni * 2];
                s_sq[wm][cl + 1]  = csq[ni * 2 + 1];
            }
        }
        __syncthreads();
        if (tid < 64) {
            float s = s_sum[0][tid] + s_sum[1][tid];
            float q = s_sq[0][tid] + s_sq[1][tid];
            bnp[blockIdx.y * NW + n0 + tid]          = s;
            bnp[4 * NW + blockIdx.y * NW + n0 + tid] = q;
        }
    }
}

// ---------------- BN apply + sigmoid with inline 4-partial finalize; optional bf16 emit ------
template <int EMIT>
__global__ void bn_apply_sig_kernel(const float* __restrict__ X, const float* __restrict__ bnp,
                                    const float* __restrict__ g, const float* __restrict__ b,
                                    float* __restrict__ Y, unsigned short* __restrict__ Ab) {
    int idx4 = blockIdx.x * blockDim.x + threadIdx.x;
    int m = idx4 >> 9, c4 = (idx4 & 511) << 2;
    float4 x  = *(const float4*)(X + (size_t)idx4 * 4);
    float4 gg = *(const float4*)(g + c4);
    float4 bb = *(const float4*)(b + c4);
    float4 mm, rs;
    {
        float4 s0 = *(const float4*)(bnp + c4);
        float4 s1 = *(const float4*)(bnp + NW + c4);
        float4 s2 = *(const float4*)(bnp + 2 * NW + c4);
        float4 s3 = *(const float4*)(bnp + 3 * NW + c4);
        float4 q0 = *(const float4*)(bnp + 4 * NW + c4);
        float4 q1 = *(const float4*)(bnp + 5 * NW + c4);
        float4 q2 = *(const float4*)(bnp + 6 * NW + c4);
        float4 q3 = *(const float4*)(bnp + 7 * NW + c4);
        mm.x = (s0.x + s1.x + s2.x + s3.x) * (1.f / 256.f);
        mm.y = (s0.y + s1.y + s2.y + s3.y) * (1.f / 256.f);
        mm.z = (s0.z + s1.z + s2.z + s3.z) * (1.f / 256.f);
        mm.w = (s0.w + s1.w + s2.w + s3.w) * (1.f / 256.f);
        rs.x = rsqrtf((q0.x + q1.x + q2.x + q3.x) * (1.f / 256.f) - mm.x * mm.x + EPS);
        rs.y = rsqrtf((q0.y + q1.y + q2.y + q3.y) * (1.f / 256.f) - mm.y * mm.y + EPS);
        rs.z = rsqrtf((q0.z + q1.z + q2.z + q3.z) * (1.f / 256.f) - mm.z * mm.z + EPS);
        rs.w = rsqrtf((q0.w + q1.w + q2.w + q3.w) * (1.f / 256.f) - mm.w * mm.w + EPS);
    }
    float4 o;
    o.x = 1.f / (1.f + expf(-((x.x - mm.x) * rs.x * gg.x + bb.x)));
    o.y = 1.f / (1.f + expf(-((x.y - mm.y) * rs.y * gg.y + bb.y)));
    o.z = 1.f / (1.f + expf(-((x.z - mm.z) * rs.z * gg.z + bb.z)));
    o.w = 1.f / (1.f + expf(-((x.w - mm.w) * rs.w * gg.w + bb.w)));
    *(float4*)(Y + (size_t)idx4 * 4) = o;
    if (EMIT) {
        uint2 hv, lv;
        f4_to_hilo(o, hv, lv);
        unsigned short* yr = Ab + (size_t)m * 4096 + c4;
        *(uint2*)yr = hv;
        *(uint2*)(yr + 2048) = lv;
    }
}

// ---------------- rho_hat = column sums of z ----------------
__global__ void colsum_part_kernel(const float* __restrict__ X, float* __restrict__ part) {
    int c = blockIdx.x * 256 + threadIdx.x;
    int r0 = blockIdx.y * 16;
    float s = 0.f;
#pragma unroll
    for (int r = 0; r < 16; r++) s += X[(size_t)(r0 + r) * NW + c];
    part[blockIdx.y * NW + c] = s;
}
__global__ void colsum_fin_kernel(const float* __restrict__ part, float* __restrict__ out) {
    int c = blockIdx.x * 256 + threadIdx.x;
    float s = 0.f;
#pragma unroll
    for (int i = 0; i < 16; i++) s += part[i * NW + c];
    out[c] = s;
}

// ---------------- misc: all_emb + y_process + rhos ----------------
__device__ __forceinline__ uint32_t rotl32(uint32_t x, uint32_t r) { return (x << r) | (x >> (32 - r)); }
__device__ __forceinline__ float tf_uniform(uint32_t bits) {
    uint32_t ub = (bits >> 9) | 0x3F800000u;
    float u = __uint_as_float(ub) - 1.0f;
    float v = u * (0.01f - 1e-5f) + 1e-5f;
    return fmaxf(1e-5f, v);
}
__global__ void misc_kernel(const float* __restrict__ embeds, float* __restrict__ allemb,
                            float* __restrict__ yp, float* __restrict__ rhos) {
    int idx = blockIdx.x * 256 + threadIdx.x;
    allemb[idx] = embeds[idx & 8191];
    if (idx < BN_NODES) yp[idx] = (float)(idx >> 13);
    if (idx < 2048) {
        const uint32_t k0 = 0u, k1 = 42u;
        uint32_t ks[3] = {k0, k1, k0 ^ k1 ^ 0x1BD11BDAu};
        uint32_t x0 = 0u + ks[0];
        uint32_t x1 = (uint32_t)idx + ks[1];
        const uint32_t rot[2][4] = {{13u, 15u, 26u, 6u}, {17u, 29u, 16u, 24u}};
#pragma unroll
        for (int r = 0; r < 5; r++) {
#pragma unroll
            for (int j = 0; j < 4; j++) {
                x0 += x1;
                x1 = rotl32(x1, rot[r & 1][j]);
                x1 ^= x0;
            }
            x0 += ks[(r + 1) % 3];
            x1 += ks[(r + 2) % 3] + (uint32_t)(r + 1);
        }
        rhos[idx] = tf_uniform(x0 ^ x1);
    }
}

// ---------------- GRU embeddings ----------------
__global__ void gru_kernel(const float* __restrict__ emb, const float* __restrict__ Wih,
                           const float* __restrict__ bih, const float* __restrict__ bhh,
                           const float* __restrict__ att_em_i, const float* __restrict__ att_em_j,
                           float* __restrict__ embeds, float* __restrict__ ei, float* __restrict__ ej) {
    int node = blockIdx.x;
    int proc = node >> 5;
    int t = threadIdx.x;
    int dir = t / 96, g = t % 96;
    __shared__ float x[64], gi[2][96], xn[64];
    if (t < 64) x[t] = emb[(size_t)node * 64 + t];
    __syncthreads();
    for (int l = 0; l < 3; l++) {
        {
            size_t base = (((size_t)proc * 3 + l) * 2 + dir) * 96 + g;
            const float* Wr = Wih + base * 64;
            float s = bih[base];
#pragma unroll
            for (int k = 0; k < 64; k++) s += Wr[k] * x[k];
            gi[dir][g] = s;
        }
        __syncthreads();
        if (g < 32) {
            int j = g;
            size_t bb = (((size_t)proc * 3 + l) * 2 + dir) * 96;
            float rh = bhh[bb + j], zh = bhh[bb + 32 + j], nh = bhh[bb + 64 + j];
            float r  = 1.f / (1.f + expf(-(gi[dir][j] + rh)));
            float zz = 1.f / (1.f + expf(-(gi[dir][32 + j] + zh)));
            float n  = tanhf(gi[dir][64 + j] + r * nh);
            xn[dir * 32 + j] = (1.f - zz) * n;
        }
        __syncthreads();
        if (t < 64) x[t] = xn[t];
        __syncthreads();
    }
    if (t < 64) embeds[(size_t)node * 64 + t] = x[t];
    if (t == 0) {
        float si = 0.f, sj = 0.f;
        for (int d = 0; d < 64; d++) { si += x[d] * att_em_i[d]; sj += x[d] * att_em_j[d]; }
        ei[node] = si; ej[node] = sj;
    }
}

// ---------------- cosine-sim top-k ----------------
__global__ void topk_kernel(const float* __restrict__ embeds, int* __restrict__ topk) {
    __shared__ float en[128][65];
    int t = threadIdx.x;
    float row[64]; float s = 0.f;
    for (int d = 0; d < 64; d++) { float v = embeds[t * 64 + d]; row[d] = v; s += v * v; }
    float nrm = sqrtf(s);
    for (int d = 0; d < 64; d++) en[t][d] = row[d] / nrm;
    __syncthreads();
    float sim[128];
    for (int j = 0; j < 128; j++) {
        float acc = 0.f;
        for (int d = 0; d < 64; d++) acc += en[t][d] * en[j][d];
        sim[j] = acc;
    }
    for (int k = 0; k < TOPK; k++) {
        float best = -1e38f; int bi = 0;
        for (int j = 0; j < 128; j++) if (sim[j] > best) { best = sim[j]; bi = j; }
        topk[t * TOPK + k] = bi;
        sim[bi] = -1e38f;
    }
}

// ---------------- x_lin + per-node attention scores ----------------
__global__ void xlin_score_kernel(const float* __restrict__ z, const float* __restrict__ W,
                                  const float* __restrict__ att_i, const float* __restrict__ att_j,
                                  const float* __restrict__ ei, const float* __restrict__ ej,
                                  float* __restrict__ xlin, float* __restrict__ si, float* __restrict__ sj) {
    __shared__ float Ws[64][17];
    __shared__ float ai[64], aj[64];
    int t = threadIdx.x;
    if (t < 64) { ai[t] = att_i[t]; aj[t] = att_j[t]; }
    for (int idx = t; idx < 1024; idx += 256) Ws[idx >> 4][idx & 15] = W[idx];
    __syncthreads();
    int warp = t >> 5, lane = t & 31;
    int v = blockIdx.x * 8 + warp;
    float zr[16];
#pragma unroll
    for (int k = 0; k < 16; k++) zr[k] = z[(size_t)v * 16 + k];
    int d0 = lane, d1 = lane + 32;
    float x0 = 0.f, x1 = 0.f;
#pragma unroll
    for (int k = 0; k < 16; k++) { x0 += zr[k] * Ws[d0][k]; x1 += zr[k] * Ws[d1][k]; }
    xlin[(size_t)v * 64 + d0] = x0;
    xlin[(size_t)v * 64 + d1] = x1;
    float pi = x0 * ai[d0] + x1 * ai[d1];
    float pj = x0 * aj[d0] + x1 * aj[d1];
#pragma unroll
    for (int o = 16; o > 0; o >>= 1) {
        pi += __shfl_xor_sync(0xFFFFFFFFu, pi, o);
        pj += __shfl_xor_sync(0xFFFFFFFFu, pj, o);
    }
    if (lane == 0) {
        int i = v & 127;
        si[v] = pi + ei[i];
        sj[v] = pj + ej[i];
    }
}

// ---------------- GAT attention aggregation ----------------
__global__ void attn_kernel(const float* __restrict__ xlin, const float* __restrict__ si,
                            const float* __restrict__ sj, const int* __restrict__ topk,
                            const float* __restrict__ bias, float* __restrict__ agg) {
    int nl = threadIdx.x >> 6;
    int t  = threadIdx.x & 63;
    int v = blockIdx.x * 4 + nl;
    int i = v & 127, b = v >> 7;
    __shared__ float w[4][32];
    __shared__ int   srcv[4][31];
    __shared__ float invden[4];
    if (t < 32) {
        float a = -3e38f;
        if (t < 31) {
            int s, valid;
            if (t < 30) { s = topk[i * TOPK + t]; valid = (s != i); }
            else        { s = i; valid = 1; }
            int sv = (b << 7) + s;
            srcv[nl][t] = sv;
            float raw = si[v] + sj[sv];
            raw = raw > 0.f ? raw : 0.2f * raw;
            a = valid ? raw : -1e30f;
        }
        float mx = a;
#pragma unroll
        for (int o = 16; o > 0; o >>= 1) mx = fmaxf(mx, __shfl_xor_sync(0xFFFFFFFFu, mx, o));
        float ee = (t < 31 && a > -1e29f) ? expf(a - mx) : 0.f;
        if (t < 31) w[nl][t] = ee;
        float den = ee;
#pragma unroll
        for (int o = 16; o > 0; o >>= 1) den += __shfl_xor_sync(0xFFFFFFFFu, den, o);
        if (t == 0) invden[nl] = 1.f / den;
    }
    __syncthreads();
    float acc = 0.f;
#pragma unroll
    for (int e = 0; e < 31; e++) acc += w[nl][e] * xlin[(size_t)srcv[nl][e] * 64 + t];
    agg[(size_t)v * 64 + t] = acc * invden[nl] + bias[t];
}

// ---------------- column stats over 32768 rows x 64 cols ----------------
__global__ void colstat_part_kernel(const float* __restrict__ x, float* __restrict__ part) {
    int c = threadIdx.x & 63, rl = threadIdx.x >> 6;
    int base = blockIdx.x * 256;
    float s = 0.f, sq = 0.f;
    for (int r = rl; r < 256; r += 4) {
        float v = x[(size_t)(base + r) * 64 + c];
        s += v; sq += v * v;
    }
    __shared__ float ss[4][64], sqv[4][64];
    ss[rl][c] = s; sqv[rl][c] = sq;
    __syncthreads();
    if (rl == 0) {
        part[blockIdx.x * 128 + c]      = ss[0][c] + ss[1][c] + ss[2][c] + ss[3][c];
        part[blockIdx.x * 128 + 64 + c] = sqv[0][c] + sqv[1][c] + sqv[2][c] + sqv[3][c];
    }
}
__global__ void colstat_fin_kernel(const float* __restrict__ part, float* __restrict__ stats) {
    int c = threadIdx.x;
    float s = 0.f, sq = 0.f;
    for (int bk = 0; bk < 128; bk++) { s += part[bk * 128 + c]; sq += part[bk * 128 + 64 + c]; }
    float m = s * (1.f / 32768.f);
    float var = sq * (1.f / 32768.f) - m * m;
    stats[c]      = m;
    stats[64 + c] = rsqrtf(var + EPS);
}

// ---------------- gnn BN + relu + mul embeds, fused tb column-stat partials ----------------
__global__ void gnnbn_mul_stat_kernel(const float* __restrict__ agg, const float* __restrict__ stats,
                                      const float* __restrict__ g, const float* __restrict__ b,
                                      const float* __restrict__ embeds, float* __restrict__ tb,
                                      float* __restrict__ part) {
    int c = threadIdx.x & 63, rl = threadIdx.x >> 6;
    int base = blockIdx.x * 256;
    float mm = stats[c], rs = stats[64 + c], gg = g[c], bb = b[c];
    float s = 0.f, sq = 0.f;
    for (int r = rl; r < 256; r += 4) {
        int row = base + r;
        float h = (agg[(size_t)row * 64 + c] - mm) * rs * gg + bb;
        h = fmaxf(h, 0.f);
        float val = h * embeds[(row & 127) * 64 + c];
        tb[(size_t)row * 64 + c] = val;
        s += val; sq += val * val;
    }
    __shared__ float ss[4][64], sqv[4][64];
    ss[rl][c] = s; sqv[rl][c] = sq;
    __syncthreads();
    if (rl == 0) {
        part[blockIdx.x * 128 + c]      = ss[0][c] + ss[1][c] + ss[2][c] + ss[3][c];
        part[blockIdx.x * 128 + 64 + c] = sqv[0][c] + sqv[1][c] + sqv[2][c] + sqv[3][c];
    }
}

// ---------------- out BN + relu + output projection ----------------
__global__ void frcst_kernel(const float* __restrict__ tb, const float* __restrict__ stats,
                             const float* __restrict__ g, const float* __restrict__ b,
                             const float* __restrict__ outW, const float* __restrict__ outb,
                             float* __restrict__ out) {
    int t = threadIdx.x;
    int warp = t >> 5, lane = t & 31;
    int v = blockIdx.x * 8 + warp;
    float acc = 0.f;
#pragma unroll
    for (int d = lane; d < 64; d += 32) {
        float val = (tb[(size_t)v * 64 + d] - stats[d]) * stats[64 + d] * g[d] + b[d];
        val = fmaxf(val, 0.f);
        acc += val * outW[d];
    }
#pragma unroll
    for (int o = 16; o > 0; o >>= 1) acc += __shfl_xor_sync(0xFFFFFFFFu, acc, o);
    if (lane == 0) out[v] = acc + outb[0];
}

// ---------------- launch ----------------
extern "C" void kernel_launch(void* const* d_in, const int* in_sizes, int n_in,
                              void* d_out, int out_size) {
    const float* data      = (const float*)d_in[0];
    const float* enc_W     = (const float*)d_in[3];
    const float* enc_b     = (const float*)d_in[4];
    const float* enc_bn_g  = (const float*)d_in[5];
    const float* enc_bn_b  = (const float*)d_in[6];
    const float* dec_W     = (const float*)d_in[7];
    const float* dec_b     = (const float*)d_in[8];
    const float* dec_bn_g  = (const float*)d_in[9];
    const float* dec_bn_b  = (const float*)d_in[10];
    const float* emb_tab   = (const float*)d_in[11];
    const float* gru_Wih   = (const float*)d_in[12];
    const float* gru_bih   = (const float*)d_in[14];
    const float* gru_bhh   = (const float*)d_in[15];
    const float* gnn_lin_W = (const float*)d_in[16];
    const float* att_i     = (const float*)d_in[17];
    const float* att_j     = (const float*)d_in[18];
    const float* att_em_i  = (const float*)d_in[19];
    const float* att_em_j  = (const float*)d_in[20];
    const float* gnn_bias  = (const float*)d_in[21];
    const float* gnn_bn_g  = (const float*)d_in[22];
    const float* gnn_bn_b  = (const float*)d_in[23];
    const float* bn_out_g  = (const float*)d_in[24];
    const float* bn_out_b  = (const float*)d_in[25];
    const float* out_W     = (const float*)d_in[26];
    const float* out_b     = (const float*)d_in[27];

    float* out = (float*)d_out;
    float* o_frcst  = out;
    float* o_recon  = o_frcst  + 32768;
    float* o_z      = o_recon  + 524288;
    float* o_encf0  = o_z      + 524288;
    float* o_decf0  = o_encf0  + 524288;
    float* o_allemb = o_decf0  + 524288;
    float* o_y      = o_allemb + 2097152;
    float* o_rhos   = o_y      + 32768;
    float* o_rhohat = o_rhos   + 2048;

    float *p_lin, *p_bnp, *p_csp, *p_emb, *p_ei, *p_ej, *p_xlin, *p_si, *p_sj,
          *p_agg, *p_tb, *p_part, *p_st1, *p_st2;
    unsigned short *p_ab, *p_wb;
    int   *p_topk, *p_flags;
    cudaGetSymbolAddress((void**)&p_lin,  d_lin);
    cudaGetSymbolAddress((void**)&p_flags, d_flags);
    cudaGetSymbolAddress((void**)&p_ab,   d_abuf);
    cudaGetSymbolAddress((void**)&p_wb,   d_wbuf4);
    cudaGetSymbolAddress((void**)&p_bnp,  d_bnp);
    cudaGetSymbolAddress((void**)&p_csp,  d_cspart);
    cudaGetSymbolAddress((void**)&p_emb,  d_embeds);
    cudaGetSymbolAddress((void**)&p_ei,   d_ei);
    cudaGetSymbolAddress((void**)&p_ej,   d_ej);
    cudaGetSymbolAddress((void**)&p_topk, d_topkbuf);
    cudaGetSymbolAddress((void**)&p_xlin, d_xlin);
    cudaGetSymbolAddress((void**)&p_si,   d_si);
    cudaGetSymbolAddress((void**)&p_sj,   d_sj);
    cudaGetSymbolAddress((void**)&p_agg,  d_agg);
    cudaGetSymbolAddress((void**)&p_tb,   d_tb);
    cudaGetSymbolAddress((void**)&p_part, d_part);
    cudaGetSymbolAddress((void**)&p_st1,  d_stats1);
    cudaGetSymbolAddress((void**)&p_st2,  d_stats2);
    unsigned short* p_w[4] = { p_wb, p_wb + (size_t)NW * 4096, p_wb + 2 * (size_t)NW * 4096,
                               p_wb + 3 * (size_t)NW * 4096 };
    const float* Wsrc[4] = { enc_W, enc_W + (size_t)NW * NW, dec_W, dec_W + (size_t)NW * NW };

    const int GEMM_SMEM = 3 * 2 * STAGE_SH * 2;   // 55296 bytes
    cudaFuncSetAttribute(gemm_mma_kernel, cudaFuncAttributeMaxDynamicSharedMemorySize, GEMM_SMEM);

    dim3 ggrid(32, 4, 4);
    dim3 csgrid(8, 16);

    // ---- streams / events: created ONCE; reused on capture call ----
    static cudaStream_t s1 = nullptr, s2 = nullptr;
    static cudaEvent_t eFork, eW[4], eZ, eSide;
    static bool inited = false;
    if (!inited) {
        cudaStreamCreateWithFlags(&s1, cudaStreamNonBlocking);
        cudaStreamCreateWithFlags(&s2, cudaStreamNonBlocking);
        cudaEventCreateWithFlags(&eFork, cudaEventDisableTiming);
        for (int i = 0; i < 4; i++) cudaEventCreateWithFlags(&eW[i], cudaEventDisableTiming);
        cudaEventCreateWithFlags(&eZ, cudaEventDisableTiming);
        cudaEventCreateWithFlags(&eSide, cudaEventDisableTiming);
        inited = true;
    }

    cudaEventRecord(eFork, 0);
    cudaStreamWaitEvent(s1, eFork, 0);
    cudaStreamWaitEvent(s2, eFork, 0);

    // ---- s1: weight conversions (each gated separately) ----
    for (int i = 0; i < 4; i++) {
        conv_hilo_kernel<<<4096, 256, 0, s1>>>(Wsrc[i], p_w[i], nullptr);
        cudaEventRecord(eW[i], s1);
    }

    // ---- s2: GRU -> topk -> misc (independent of encoder) ----
    gru_kernel<<<128, 192, 0, s2>>>(emb_tab, gru_Wih, gru_bih, gru_bhh, att_em_i, att_em_j,
                                    p_emb, p_ei, p_ej);
    topk_kernel<<<1, 128, 0, s2>>>(p_emb, p_topk);
    misc_kernel<<<8192, 256, 0, s2>>>(p_emb, o_allemb, o_y, o_rhos);

    // ---- main: encoder (convA also clears all layers' chain flags) ----
    conv_hilo_kernel<<<512, 256>>>(data, p_ab, p_flags);
    cudaStreamWaitEvent(0, eW[0], 0);
    gemm_mma_kernel<<<ggrid, 128, GEMM_SMEM>>>(p_ab, p_w[0], enc_b, p_lin, p_bnp, p_flags);
    bn_apply_sig_kernel<1><<<512, 256>>>(p_lin, p_bnp, enc_bn_g, enc_bn_b, o_encf0, p_ab);
    cudaStreamWaitEvent(0, eW[1], 0);
    gemm_mma_kernel<<<ggrid, 128, GEMM_SMEM>>>(p_ab, p_w[1], enc_b + NW, p_lin, p_bnp, p_flags + 128);
    bn_apply_sig_kernel<1><<<512, 256>>>(p_lin, p_bnp, enc_bn_g + NW, enc_bn_b + NW, o_z, p_ab);
    cudaEventRecord(eZ, 0);

    // ---- s2: after z ready — colsum + full GNN chain, parallel with decoder ----
    cudaStreamWaitEvent(s2, eZ, 0);
    colsum_part_kernel<<<csgrid, 256, 0, s2>>>(o_z, p_csp);
    colsum_fin_kernel<<<8, 256, 0, s2>>>(p_csp, o_rhohat);
    xlin_score_kernel<<<4096, 256, 0, s2>>>(o_z, gnn_lin_W, att_i, att_j, p_ei, p_ej,
                                            p_xlin, p_si, p_sj);
    attn_kernel<<<8192, 256, 0, s2>>>(p_xlin, p_si, p_sj, p_topk, gnn_bias, p_agg);
    colstat_part_kernel<<<128, 256, 0, s2>>>(p_agg, p_part);
    colstat_fin_kernel<<<1, 64, 0, s2>>>(p_part, p_st1);
    gnnbn_mul_stat_kernel<<<128, 256, 0, s2>>>(p_agg, p_st1, gnn_bn_g, gnn_bn_b, p_emb, p_tb, p_part);
    colstat_fin_kernel<<<1, 64, 0, s2>>>(p_part, p_st2);
    frcst_kernel<<<4096, 256, 0, s2>>>(p_tb, p_st2, bn_out_g, bn_out_b, out_W, out_b, o_frcst);
    cudaEventRecord(eSide, s2);

    // ---- main: decoder ----
    cudaStreamWaitEvent(0, eW[2], 0);
    gemm_mma_kernel<<<ggrid, 128, GEMM_SMEM>>>(p_ab, p_w[2], dec_b, p_lin, p_bnp, p_flags + 256);
    bn_apply_sig_kernel<1><<<512, 256>>>(p_lin, p_bnp, dec_bn_g, dec_bn_b, o_decf0, p_ab);
    cudaStreamWaitEvent(0, eW[3], 0);
    gemm_mma_kernel<<<ggrid, 128, GEMM_SMEM>>>(p_ab, p_w[3], dec_b + NW, p_lin, p_bnp, p_flags + 384);
    bn_apply_sig_kernel<0><<<512, 256>>>(p_lin, p_bnp, dec_bn_g + NW, dec_bn_b + NW, o_recon, nullptr);

    // ---- join side branch back to origin stream ----
    cudaStreamWaitEvent(0, eSide, 0);
}